// round 1
// baseline (speedup 1.0000x reference)
#include <cuda_runtime.h>
#include <math.h>

// ---------------------------------------------------------------------------
// Model constants
//   x: (32,54,54)  conv1: 256f 6x6 s2 -> (32,256,25,25)
//   conv2: 256->256 6x6 s1 on pad(2,3) -> (32,256,25,25)
//   conv3: 1x1 512->256 on concat
//   caps: (32, 20000, 8);  u_hat: (32,20000,8,16);  routing 3 iters
// ---------------------------------------------------------------------------
#define B_SZ   32
#define NCAPS  20000

// Scratch (static device allocations only — no cudaMalloc allowed)
__device__ float g_xp[32 * 30 * 30 * 256];     // padded x1, channels-last  (29.5 MB)
__device__ float g_zc[20000 * 512];            // [x1 | conv2out] channels-last (41 MB)
__device__ float g_w2t[36 * 256 * 256];        // conv2 weights (khw, ic, oc)
__device__ float g_w3t[512 * 256];             // conv3 weights (ic, oc)
__device__ float g_c3[20000 * 256];            // conv3 out per pixel (b*625+hw, oc)
__device__ float g_uhat[32 * 20000 * 128];     // (b, n, e*16+o)  (327 MB)
__device__ float g_logits[32 * 20000 * 8];     // routing logits
__device__ float g_S0[32 * 128];
__device__ float g_S1[32 * 128];
__device__ float g_S2[32 * 128];
__device__ float g_v[32 * 128];                // (b, e*16+o)

// ---------------------------------------------------------------------------
__global__ void k_zero_all() {
    int i = blockIdx.x * 256 + threadIdx.x;
    if (i < 32 * 30 * 30 * 256) g_xp[i] = 0.f;
    if (i < 32 * 20000 * 8)     g_logits[i] = 0.f;
    if (i < 32 * 128) { g_S0[i] = 0.f; g_S1[i] = 0.f; g_S2[i] = 0.f; }
}

// conv1 + relu -> xp (padded interior) and zc[:, 0:256]
__global__ void k_conv1(const float* __restrict__ x,
                        const float* __restrict__ w1,
                        const float* __restrict__ b1) {
    __shared__ float xs[36];
    int blk = blockIdx.x;               // 0..19999 : (b, oh, ow)
    int b = blk / 625, p = blk % 625, oh = p / 25, ow = p % 25;
    int t = threadIdx.x;                // 256 = oc
    if (t < 36) {
        int kh = t / 6, kw = t % 6;
        xs[t] = x[b * 2916 + (2 * oh + kh) * 54 + (2 * ow + kw)];
    }
    __syncthreads();
    float acc = b1[t];
#pragma unroll
    for (int j = 0; j < 36; j++) acc += xs[j] * __ldg(&w1[t * 36 + j]);
    acc = fmaxf(acc, 0.f);
    g_xp[((b * 30 + oh + 2) * 30 + (ow + 2)) * 256 + t] = acc;
    g_zc[(b * 625 + oh * 25 + ow) * 512 + t] = acc;
}

// weight reorg: conv2_w (oc,ic,kh,kw) -> g_w2t[khw][ic][oc]
__global__ void k_prep_w2(const float* __restrict__ w2) {
    int i = blockIdx.x * 256 + threadIdx.x;     // 36*256*256 = 2359296
    if (i < 2359296) {
        int oc = i & 255;
        int ic = (i >> 8) & 255;
        int khw = i >> 16;
        g_w2t[i] = w2[oc * 9216 + ic * 36 + khw];
    }
}
// conv3_w (oc, ic) -> g_w3t[ic][oc]
__global__ void k_prep_w3(const float* __restrict__ w3) {
    int i = blockIdx.x * 256 + threadIdx.x;     // 131072
    if (i < 131072) {
        int oc = i & 255, ic = i >> 8;
        g_w3t[i] = w3[oc * 512 + ic];
    }
}

// ---------------------------------------------------------------------------
// conv2 implicit GEMM: C[20000][256] = im2col(xp)[20000][9216] * w2t[9216][256]
// BM=BN=64, BK=16, 128 threads, 8x4 register tile.
// ---------------------------------------------------------------------------
__global__ void k_conv2(const float* __restrict__ b2) {
    __shared__ float As[16][64];
    __shared__ float Bs[16][64];
    __shared__ int rowbase[64];
    int tid = threadIdx.x;
    int m0 = blockIdx.x * 64, n0 = blockIdx.y * 64;

    if (tid < 64) {
        int m = m0 + tid;
        if (m < 20000) {
            int b = m / 625, p = m % 625, oh = p / 25, ow = p % 25;
            rowbase[tid] = ((b * 30 + oh) * 30 + ow) * 256;
        } else rowbase[tid] = -1;
    }
    __syncthreads();

    float acc[8][4];
#pragma unroll
    for (int i = 0; i < 8; i++)
#pragma unroll
        for (int j = 0; j < 4; j++) acc[i][j] = 0.f;

    int tm = (tid >> 4) << 3;          // 0..56
    int tn = (tid & 15) << 2;          // 0..60
    int lr = tid >> 2, lq = tid & 3;   // A loader: row / quad
    int bk = tid >> 4, bc = (tid & 15) << 2;  // B loader

    for (int k0 = 0; k0 < 9216; k0 += 16) {
        int khw = k0 >> 8;
        int kh = khw / 6, kw = khw - kh * 6;
        int koff = (kh * 30 + kw) * 256 + (k0 & 255) + lq * 4;
#pragma unroll
        for (int ps = 0; ps < 2; ps++) {
            int r = lr + ps * 32;
            float4 v = make_float4(0.f, 0.f, 0.f, 0.f);
            int rb = rowbase[r];
            if (rb >= 0) v = *(const float4*)&g_xp[rb + koff];
            As[lq * 4 + 0][r] = v.x;
            As[lq * 4 + 1][r] = v.y;
            As[lq * 4 + 2][r] = v.z;
            As[lq * 4 + 3][r] = v.w;
        }
#pragma unroll
        for (int ps = 0; ps < 2; ps++) {
            int kk = bk + ps * 8;
            *(float4*)&Bs[kk][bc] = *(const float4*)&g_w2t[(k0 + kk) * 256 + n0 + bc];
        }
        __syncthreads();
#pragma unroll
        for (int k = 0; k < 16; k++) {
            float4 a0 = *(const float4*)&As[k][tm];
            float4 a1 = *(const float4*)&As[k][tm + 4];
            float4 bb = *(const float4*)&Bs[k][tn];
            float a[8] = {a0.x, a0.y, a0.z, a0.w, a1.x, a1.y, a1.z, a1.w};
            float bf[4] = {bb.x, bb.y, bb.z, bb.w};
#pragma unroll
            for (int i = 0; i < 8; i++)
#pragma unroll
                for (int j = 0; j < 4; j++) acc[i][j] += a[i] * bf[j];
        }
        __syncthreads();
    }
#pragma unroll
    for (int i = 0; i < 8; i++) {
        int m = m0 + tm + i;
        if (m < 20000) {
#pragma unroll
            for (int j = 0; j < 4; j++) {
                float v = acc[i][j] + b2[n0 + tn + j];
                g_zc[m * 512 + 256 + n0 + tn + j] = fmaxf(v, 0.f);
            }
        }
    }
}

// conv3 plain GEMM: C[20000][256] = zc[20000][512] * w3t[512][256] + b3
__global__ void k_conv3(const float* __restrict__ b3) {
    __shared__ float As[16][64];
    __shared__ float Bs[16][64];
    int tid = threadIdx.x;
    int m0 = blockIdx.x * 64, n0 = blockIdx.y * 64;

    float acc[8][4];
#pragma unroll
    for (int i = 0; i < 8; i++)
#pragma unroll
        for (int j = 0; j < 4; j++) acc[i][j] = 0.f;

    int tm = (tid >> 4) << 3;
    int tn = (tid & 15) << 2;
    int lr = tid >> 2, lq = tid & 3;
    int bk = tid >> 4, bc = (tid & 15) << 2;

    for (int k0 = 0; k0 < 512; k0 += 16) {
#pragma unroll
        for (int ps = 0; ps < 2; ps++) {
            int r = lr + ps * 32;
            int m = m0 + r;
            float4 v = make_float4(0.f, 0.f, 0.f, 0.f);
            if (m < 20000) v = *(const float4*)&g_zc[m * 512 + k0 + lq * 4];
            As[lq * 4 + 0][r] = v.x;
            As[lq * 4 + 1][r] = v.y;
            As[lq * 4 + 2][r] = v.z;
            As[lq * 4 + 3][r] = v.w;
        }
#pragma unroll
        for (int ps = 0; ps < 2; ps++) {
            int kk = bk + ps * 8;
            *(float4*)&Bs[kk][bc] = *(const float4*)&g_w3t[(k0 + kk) * 256 + n0 + bc];
        }
        __syncthreads();
#pragma unroll
        for (int k = 0; k < 16; k++) {
            float4 a0 = *(const float4*)&As[k][tm];
            float4 a1 = *(const float4*)&As[k][tm + 4];
            float4 bb = *(const float4*)&Bs[k][tn];
            float a[8] = {a0.x, a0.y, a0.z, a0.w, a1.x, a1.y, a1.z, a1.w};
            float bf[4] = {bb.x, bb.y, bb.z, bb.w};
#pragma unroll
            for (int i = 0; i < 8; i++)
#pragma unroll
                for (int j = 0; j < 4; j++) acc[i][j] += a[i] * bf[j];
        }
        __syncthreads();
    }
#pragma unroll
    for (int i = 0; i < 8; i++) {
        int m = m0 + tm + i;
        if (m < 20000) {
#pragma unroll
            for (int j = 0; j < 4; j++)
                g_c3[m * 256 + n0 + tn + j] = acc[i][j] + b3[n0 + tn + j];
        }
    }
}

// ---------------------------------------------------------------------------
// capsules: u = caps @ pc_w^T + pc_b ; u_hat = u @ W^T  (per capsule n, all b)
// block per n (20000), 128 threads = (e,o) pairs
// ---------------------------------------------------------------------------
__global__ void k_caps(const float* __restrict__ pcw,
                       const float* __restrict__ pcb,
                       const float* __restrict__ W) {
    __shared__ float s_pcw[64];
    __shared__ float s_pcb[8];
    __shared__ float s_caps[32][8];
    __shared__ float s_u[32][8];
    int n = blockIdx.x;
    int t = threadIdx.x;
    int g = n / 625, hw = n - g * 625;

    if (t < 64) s_pcw[t] = pcw[n * 64 + t];
    if (t < 8)  s_pcb[t] = pcb[n * 8 + t];
#pragma unroll
    for (int r = 0; r < 2; r++) {
        int idx = t + r * 128;          // b*8 + i
        int b = idx >> 3, i = idx & 7;
        s_caps[b][i] = g_c3[(b * 625 + hw) * 256 + g * 8 + i];
    }
    __syncthreads();
#pragma unroll
    for (int r = 0; r < 2; r++) {
        int idx = t + r * 128;          // b*8 + o
        int b = idx >> 3, o = idx & 7;
        float u = s_pcb[o];
#pragma unroll
        for (int i = 0; i < 8; i++) u += s_caps[b][i] * s_pcw[o * 8 + i];
        s_u[b][o] = u;
    }
    __syncthreads();
    // t = e*16 + o;  W[n, e, o, i] at n*1024 + t*8 + i
    float w[8];
    const float* wp = W + n * 1024 + t * 8;
#pragma unroll
    for (int i = 0; i < 8; i++) w[i] = wp[i];
#pragma unroll 4
    for (int b = 0; b < 32; b++) {
        float uh = 0.f;
#pragma unroll
        for (int i = 0; i < 8; i++) uh += s_u[b][i] * w[i];
        g_uhat[(b * 20000 + n) * 128 + t] = uh;
    }
}

// iteration 0: uniform c -> just sum u_hat over n
__global__ void k_route0() {
    int b = blockIdx.y, t = threadIdx.x;
    int n0 = blockIdx.x * 313;
    int n1 = min(20000, n0 + 313);
    float acc = 0.f;
    const float* up = g_uhat + (b * 20000) * 128 + t;
    for (int n = n0; n < n1; n++) acc += up[n * 128];
    atomicAdd(&g_S0[b * 128 + t], acc);
}

// fused: logits += u_hat . v ; c = softmax(logits) ; S += c * u_hat
__global__ void k_route_upd(int which) {
    __shared__ float vsh[128];
    __shared__ float sa[8];
    __shared__ float se[8];
    int b = blockIdx.y, t = threadIdx.x;
    int e = t >> 4, o = t & 15;
    int n0 = blockIdx.x * 313;
    int n1 = min(20000, n0 + 313);
    vsh[t] = g_v[b * 128 + t];
    __syncthreads();
    float accS = 0.f;
    for (int n = n0; n < n1; n++) {
        float uh = g_uhat[(b * 20000 + n) * 128 + t];
        float pr = uh * vsh[t];
#pragma unroll
        for (int off = 8; off; off >>= 1)
            pr += __shfl_xor_sync(0xffffffffu, pr, off);
        if (o == 0) {
            float a = g_logits[(b * 20000 + n) * 8 + e] + pr;
            g_logits[(b * 20000 + n) * 8 + e] = a;
            sa[e] = a;
        }
        __syncthreads();
        if (t < 8) {
            float amax = sa[0];
#pragma unroll
            for (int j = 1; j < 8; j++) amax = fmaxf(amax, sa[j]);
            se[t] = expf(sa[t] - amax);
        }
        __syncthreads();
        float Z = se[0] + se[1] + se[2] + se[3] + se[4] + se[5] + se[6] + se[7];
        accS += (se[e] / Z) * uh;
    }
    float* Sout = (which == 1) ? g_S1 : g_S2;
    atomicAdd(&Sout[b * 128 + t], accS);
}

__global__ void k_squash(int which, float scale) {
    int b = blockIdx.x, t = threadIdx.x;
    const float* S = (which == 0) ? g_S0 : (which == 1) ? g_S1 : g_S2;
    float s = S[b * 128 + t] * scale;
    float n2 = s * s;
#pragma unroll
    for (int off = 8; off; off >>= 1)
        n2 += __shfl_xor_sync(0xffffffffu, n2, off);
    float nn = sqrtf(n2);
    g_v[b * 128 + t] = (n2 / (1.f + n2)) * s / (nn + 1e-8f);
}

__global__ void k_final(float* __restrict__ out) {
    int b = blockIdx.x, t = threadIdx.x;
    float v = g_v[b * 128 + t];
    float s = v * v;
#pragma unroll
    for (int off = 8; off; off >>= 1)
        s += __shfl_xor_sync(0xffffffffu, s, off);
    if ((t & 15) == 0) out[b * 8 + (t >> 4)] = sqrtf(s);
}

// ---------------------------------------------------------------------------
extern "C" void kernel_launch(void* const* d_in, const int* in_sizes, int n_in,
                              void* d_out, int out_size) {
    const float* x   = (const float*)d_in[0];
    const float* w1  = (const float*)d_in[1];
    const float* b1  = (const float*)d_in[2];
    const float* w2  = (const float*)d_in[3];
    const float* b2  = (const float*)d_in[4];
    const float* w3  = (const float*)d_in[5];
    const float* b3  = (const float*)d_in[6];
    const float* pcw = (const float*)d_in[7];
    const float* pcb = (const float*)d_in[8];
    const float* W   = (const float*)d_in[9];
    float* out = (float*)d_out;

    k_zero_all<<<28800, 256>>>();
    k_conv1<<<20000, 256>>>(x, w1, b1);
    k_prep_w2<<<9216, 256>>>(w2);
    k_prep_w3<<<512, 256>>>(w3);
    k_conv2<<<dim3(313, 4), 128>>>(b2);
    k_conv3<<<dim3(313, 4), 128>>>(b3);
    k_caps<<<20000, 128>>>(pcw, pcb, W);
    k_route0<<<dim3(64, 32), 128>>>();
    k_squash<<<32, 128>>>(0, 0.125f);
    k_route_upd<<<dim3(64, 32), 128>>>(1);
    k_squash<<<32, 128>>>(1, 1.f);
    k_route_upd<<<dim3(64, 32), 128>>>(2);
    k_squash<<<32, 128>>>(2, 1.f);
    k_final<<<32, 128>>>(out);
}

// round 3
// speedup vs baseline: 1.2047x; 1.2047x over previous
#include <cuda_runtime.h>
#include <cuda_bf16.h>
#include <math.h>

// ---------------------------------------------------------------------------
//   x: (32,54,54)  conv1: 256f 6x6 s2 -> (32,256,25,25)
//   conv2: 256->256 6x6 s1 on pad(2,3) -> implicit GEMM M=20000,N=256,K=9216
//   conv3: 1x1 512->256 -> GEMM K=512
//   caps -> u_hat (32,20000,8,16) -> 3-iter dynamic routing
// ---------------------------------------------------------------------------

__device__ float g_xp[32 * 30 * 30 * 256];     // padded conv1 out, channels-last
__device__ float g_zc[20000 * 512];            // [x1 | conv2out] channels-last
__device__ float g_w2t[36 * 256 * 256];        // conv2 weights (khw, ic, oc)
__device__ float g_w3t[512 * 256];             // conv3 weights (ic, oc)
__device__ float g_c3[20000 * 256];            // conv3 out
__device__ float g_uhat[32 * 20000 * 128];     // (b, n, e*16+o)
__device__ float g_logits[32 * 20000 * 8];
__device__ float g_S0[32 * 128];
__device__ float g_S1[32 * 128];
__device__ float g_S2[32 * 128];
__device__ float g_v[32 * 128];

// ---------------------------------------------------------------------------
__global__ void k_zero_all() {
    int i = blockIdx.x * 256 + threadIdx.x;
    if (i < 32 * 30 * 30 * 256) g_xp[i] = 0.f;
    if (i < 32 * 20000 * 8)     g_logits[i] = 0.f;
    if (i < 32 * 128) { g_S0[i] = 0.f; g_S1[i] = 0.f; g_S2[i] = 0.f; }
}

__global__ void k_conv1(const float* __restrict__ x,
                        const float* __restrict__ w1,
                        const float* __restrict__ b1) {
    __shared__ float xs[36];
    int blk = blockIdx.x;
    int b = blk / 625, p = blk % 625, oh = p / 25, ow = p % 25;
    int t = threadIdx.x;
    if (t < 36) {
        int kh = t / 6, kw = t % 6;
        xs[t] = x[b * 2916 + (2 * oh + kh) * 54 + (2 * ow + kw)];
    }
    __syncthreads();
    float acc = b1[t];
#pragma unroll
    for (int j = 0; j < 36; j++) acc += xs[j] * __ldg(&w1[t * 36 + j]);
    acc = fmaxf(acc, 0.f);
    g_xp[((b * 30 + oh + 2) * 30 + (ow + 2)) * 256 + t] = acc;
    g_zc[(b * 625 + oh * 25 + ow) * 512 + t] = acc;
}

__global__ void k_prep_w2(const float* __restrict__ w2) {
    int i = blockIdx.x * 256 + threadIdx.x;
    if (i < 2359296) {
        int oc = i & 255;
        int ic = (i >> 8) & 255;
        int khw = i >> 16;
        g_w2t[i] = w2[oc * 9216 + ic * 36 + khw];
    }
}
__global__ void k_prep_w3(const float* __restrict__ w3) {
    int i = blockIdx.x * 256 + threadIdx.x;
    if (i < 131072) {
        int oc = i & 255, ic = i >> 8;
        g_w3t[i] = w3[oc * 512 + ic];
    }
}

// ---------------------------------------------------------------------------
// Tensor-core GEMM (bf16 split x3 = fp32-accurate).
// C[M][256] = A[M][K] * B[K][256];  MODE 0: conv2 implicit im2col, MODE 1: conv3.
// Block tile 128x128, BK=16, 256 threads (8 warps, warp tile 64x32).
// ---------------------------------------------------------------------------
#define AP 34   // A smem row pad (bf16 units)
#define BP 18   // B smem row pad

__device__ __forceinline__ void mma16816(float& c0, float& c1, float& c2, float& c3,
                                         unsigned a0, unsigned a1, unsigned a2, unsigned a3,
                                         unsigned b0, unsigned b1) {
    asm volatile("mma.sync.aligned.m16n8k16.row.col.f32.bf16.bf16.f32 "
                 "{%0,%1,%2,%3}, {%4,%5,%6,%7}, {%8,%9}, {%0,%1,%2,%3};"
                 : "+f"(c0), "+f"(c1), "+f"(c2), "+f"(c3)
                 : "r"(a0), "r"(a1), "r"(a2), "r"(a3), "r"(b0), "r"(b1));
}

__device__ __forceinline__ void bf_split(float v, unsigned short& h, unsigned short& l) {
    __nv_bfloat16 bh = __float2bfloat16_rn(v);
    float r = v - __bfloat162float(bh);
    __nv_bfloat16 bl = __float2bfloat16_rn(r);
    h = *(unsigned short*)&bh;
    l = *(unsigned short*)&bl;
}

template<int MODE>
__global__ void __launch_bounds__(256, 1) k_gemm_mma(const float* __restrict__ bias) {
    __shared__ unsigned short sAh[128 * AP];
    __shared__ unsigned short sAl[128 * AP];
    __shared__ unsigned short sBh[128 * BP];
    __shared__ unsigned short sBl[128 * BP];
    __shared__ int s_rowbase[128];

    const int K = (MODE == 0) ? 9216 : 512;
    const int S = K / 16;
    int tid = threadIdx.x;
    int m0 = blockIdx.x * 128;
    int n0 = blockIdx.y * 128;

    if (MODE == 0 && tid < 128) {
        int m = m0 + tid;
        if (m < 20000) {
            int b = m / 625, p = m % 625, oh = p / 25, ow = p % 25;
            s_rowbase[tid] = ((b * 30 + oh) * 30 + ow) * 256;
        } else s_rowbase[tid] = -1;
    }
    __syncthreads();

    int w = tid >> 5, lane = tid & 31;
    int grp = lane >> 2, q = lane & 3;
    int wm = (w >> 2) * 64, wn = (w & 3) * 32;

    float acc[4][4][4];
#pragma unroll
    for (int i = 0; i < 4; i++)
#pragma unroll
        for (int j = 0; j < 4; j++)
#pragma unroll
            for (int c = 0; c < 4; c++) acc[i][j][c] = 0.f;

    // loader indices
    int a_m[2], a_f4[2], b_kk[2], b_n4[2];
#pragma unroll
    for (int i = 0; i < 2; i++) {
        int slot = tid + i * 256;
        a_m[i] = slot >> 2;  a_f4[i] = slot & 3;
        b_kk[i] = slot >> 5; b_n4[i] = slot & 31;
    }

    float4 aR[2], bR[2];

    auto load_stage = [&](int s) {
        int k0 = s * 16;
#pragma unroll
        for (int i = 0; i < 2; i++) {
            float4 v = make_float4(0.f, 0.f, 0.f, 0.f);
            if (MODE == 0) {
                int khw = k0 >> 8;
                int kh = khw / 6, kw = khw - kh * 6;
                int rb = s_rowbase[a_m[i]];
                if (rb >= 0)
                    v = *(const float4*)&g_xp[rb + (kh * 30 + kw) * 256 + (k0 & 255) + a_f4[i] * 4];
            } else {
                int m = m0 + a_m[i];
                if (m < 20000)
                    v = *(const float4*)&g_zc[m * 512 + k0 + a_f4[i] * 4];
            }
            aR[i] = v;
            const float* Bsrc = (MODE == 0) ? g_w2t : g_w3t;
            bR[i] = *(const float4*)&Bsrc[(k0 + b_kk[i]) * 256 + n0 + b_n4[i] * 4];
        }
    };

    auto sts_stage = [&]() {
#pragma unroll
        for (int i = 0; i < 2; i++) {
            unsigned short h[4], l[4];
            bf_split(aR[i].x, h[0], l[0]); bf_split(aR[i].y, h[1], l[1]);
            bf_split(aR[i].z, h[2], l[2]); bf_split(aR[i].w, h[3], l[3]);
            int base = a_m[i] * AP + a_f4[i] * 4;
            *(unsigned*)&sAh[base]     = (unsigned)h[0] | ((unsigned)h[1] << 16);
            *(unsigned*)&sAh[base + 2] = (unsigned)h[2] | ((unsigned)h[3] << 16);
            *(unsigned*)&sAl[base]     = (unsigned)l[0] | ((unsigned)l[1] << 16);
            *(unsigned*)&sAl[base + 2] = (unsigned)l[2] | ((unsigned)l[3] << 16);

            bf_split(bR[i].x, h[0], l[0]); bf_split(bR[i].y, h[1], l[1]);
            bf_split(bR[i].z, h[2], l[2]); bf_split(bR[i].w, h[3], l[3]);
#pragma unroll
            for (int j = 0; j < 4; j++) {
                sBh[(b_n4[i] * 4 + j) * BP + b_kk[i]] = h[j];
                sBl[(b_n4[i] * 4 + j) * BP + b_kk[i]] = l[j];
            }
        }
    };

    load_stage(0);
    sts_stage();
    __syncthreads();

    for (int s = 0; s < S; s++) {
        if (s + 1 < S) load_stage(s + 1);

        unsigned ah[4][4], al[4][4], bh[4][2], bl[4][2];
#pragma unroll
        for (int mi = 0; mi < 4; mi++) {
            int r0 = (wm + mi * 16 + grp) * AP;
            int r1 = (wm + mi * 16 + grp + 8) * AP;
            ah[mi][0] = *(const unsigned*)&sAh[r0 + 2 * q];
            ah[mi][1] = *(const unsigned*)&sAh[r1 + 2 * q];
            ah[mi][2] = *(const unsigned*)&sAh[r0 + 2 * q + 8];
            ah[mi][3] = *(const unsigned*)&sAh[r1 + 2 * q + 8];
            al[mi][0] = *(const unsigned*)&sAl[r0 + 2 * q];
            al[mi][1] = *(const unsigned*)&sAl[r1 + 2 * q];
            al[mi][2] = *(const unsigned*)&sAl[r0 + 2 * q + 8];
            al[mi][3] = *(const unsigned*)&sAl[r1 + 2 * q + 8];
        }
#pragma unroll
        for (int ni = 0; ni < 4; ni++) {
            int c0 = (wn + ni * 8 + grp) * BP;
            bh[ni][0] = *(const unsigned*)&sBh[c0 + 2 * q];
            bh[ni][1] = *(const unsigned*)&sBh[c0 + 2 * q + 8];
            bl[ni][0] = *(const unsigned*)&sBl[c0 + 2 * q];
            bl[ni][1] = *(const unsigned*)&sBl[c0 + 2 * q + 8];
        }
#pragma unroll
        for (int mi = 0; mi < 4; mi++)
#pragma unroll
            for (int ni = 0; ni < 4; ni++) {
                float* c = acc[mi][ni];
                mma16816(c[0], c[1], c[2], c[3], ah[mi][0], ah[mi][1], ah[mi][2], ah[mi][3],
                         bh[ni][0], bh[ni][1]);
                mma16816(c[0], c[1], c[2], c[3], ah[mi][0], ah[mi][1], ah[mi][2], ah[mi][3],
                         bl[ni][0], bl[ni][1]);
                mma16816(c[0], c[1], c[2], c[3], al[mi][0], al[mi][1], al[mi][2], al[mi][3],
                         bh[ni][0], bh[ni][1]);
            }
        __syncthreads();
        if (s + 1 < S) { sts_stage(); }
        __syncthreads();
    }

    // epilogue
#pragma unroll
    for (int mi = 0; mi < 4; mi++) {
#pragma unroll
        for (int ni = 0; ni < 4; ni++) {
            int col = n0 + wn + ni * 8 + 2 * q;
            float bb0 = bias[col], bb1 = bias[col + 1];
            int row0 = m0 + wm + mi * 16 + grp;
            int row1 = row0 + 8;
            float* c = acc[mi][ni];
            if (MODE == 0) {
                if (row0 < 20000) {
                    float2 v = make_float2(fmaxf(c[0] + bb0, 0.f), fmaxf(c[1] + bb1, 0.f));
                    *(float2*)&g_zc[row0 * 512 + 256 + col] = v;
                }
                if (row1 < 20000) {
                    float2 v = make_float2(fmaxf(c[2] + bb0, 0.f), fmaxf(c[3] + bb1, 0.f));
                    *(float2*)&g_zc[row1 * 512 + 256 + col] = v;
                }
            } else {
                if (row0 < 20000)
                    *(float2*)&g_c3[row0 * 256 + col] = make_float2(c[0] + bb0, c[1] + bb1);
                if (row1 < 20000)
                    *(float2*)&g_c3[row1 * 256 + col] = make_float2(c[2] + bb0, c[3] + bb1);
            }
        }
    }
}

// ---------------------------------------------------------------------------
// capsules: u = caps @ pc_w^T + pc_b ; u_hat = u @ W^T
// ---------------------------------------------------------------------------
__global__ void k_caps(const float* __restrict__ pcw,
                       const float* __restrict__ pcb,
                       const float* __restrict__ W) {
    __shared__ float s_pcw[64];
    __shared__ float s_pcb[8];
    __shared__ float s_caps[32][8];
    __shared__ float s_u[32][8];
    int n = blockIdx.x;
    int t = threadIdx.x;
    int g = n / 625, hw = n - g * 625;

    if (t < 64) s_pcw[t] = pcw[n * 64 + t];
    if (t < 8)  s_pcb[t] = pcb[n * 8 + t];
#pragma unroll
    for (int r = 0; r < 2; r++) {
        int idx = t + r * 128;
        int b = idx >> 3, i = idx & 7;
        s_caps[b][i] = g_c3[(b * 625 + hw) * 256 + g * 8 + i];
    }
    __syncthreads();
#pragma unroll
    for (int r = 0; r < 2; r++) {
        int idx = t + r * 128;
        int b = idx >> 3, o = idx & 7;
        float u = s_pcb[o];
#pragma unroll
        for (int i = 0; i < 8; i++) u += s_caps[b][i] * s_pcw[o * 8 + i];
        s_u[b][o] = u;
    }
    __syncthreads();
    float wreg[8];
    const float* wp = W + n * 1024 + t * 8;
#pragma unroll
    for (int i = 0; i < 8; i++) wreg[i] = wp[i];
#pragma unroll 4
    for (int b = 0; b < 32; b++) {
        float uh = 0.f;
#pragma unroll
        for (int i = 0; i < 8; i++) uh += s_u[b][i] * wreg[i];
        g_uhat[(b * 20000 + n) * 128 + t] = uh;
    }
}

// iteration 0: uniform coupling -> plain sum over n
__global__ void k_route0() {
    int b = blockIdx.y, t = threadIdx.x;
    int n0 = blockIdx.x * 313;
    int n1 = min(20000, n0 + 313);
    float acc = 0.f;
    const float* up = g_uhat + (b * 20000) * 128 + t;
    for (int n = n0; n < n1; n++) acc += up[n * 128];
    atomicAdd(&g_S0[b * 128 + t], acc);
}

// fused warp-synchronous: logits += u_hat.v ; c = softmax(logits) ; S += c*u_hat
__global__ void k_route_upd(int which) {
    int b = blockIdx.y;
    int wid_g = blockIdx.x * 8 + (threadIdx.x >> 5);
    int lane = threadIdx.x & 31;
    int o = lane & 15, eh = lane >> 4;
    int n0 = wid_g * 100, n1 = min(20000, n0 + 100);

    float vv[4];
#pragma unroll
    for (int ep = 0; ep < 4; ep++) vv[ep] = g_v[b * 128 + 32 * ep + lane];

    float accS[4] = {0.f, 0.f, 0.f, 0.f};

    for (int n = n0; n < n1; n++) {
        const float* up = g_uhat + (size_t)(b * 20000 + n) * 128;
        float uh[4], dot[4];
#pragma unroll
        for (int ep = 0; ep < 4; ep++) {
            uh[ep] = up[32 * ep + lane];
            float p = uh[ep] * vv[ep];
#pragma unroll
            for (int off = 8; off; off >>= 1)
                p += __shfl_xor_sync(0xffffffffu, p, off);
            dot[ep] = p;
        }
        size_t lb = (size_t)(b * 20000 + n) * 8;
        float old[4];
        if (o == 0) {
#pragma unroll
            for (int ep = 0; ep < 4; ep++) old[ep] = g_logits[lb + 2 * ep + eh];
        }
        float a[4], m4 = -1e30f;
#pragma unroll
        for (int ep = 0; ep < 4; ep++) {
            float ob = __shfl_sync(0xffffffffu, old[ep], lane & 16);
            a[ep] = ob + dot[ep];
            m4 = fmaxf(m4, a[ep]);
        }
        if (o == 0) {
#pragma unroll
            for (int ep = 0; ep < 4; ep++) g_logits[lb + 2 * ep + eh] = a[ep];
        }
        float amax = fmaxf(m4, __shfl_xor_sync(0xffffffffu, m4, 16));
        float ex[4], s4 = 0.f;
#pragma unroll
        for (int ep = 0; ep < 4; ep++) { ex[ep] = __expf(a[ep] - amax); s4 += ex[ep]; }
        float Z = s4 + __shfl_xor_sync(0xffffffffu, s4, 16);
        float rZ = 1.f / Z;
#pragma unroll
        for (int ep = 0; ep < 4; ep++) accS[ep] += ex[ep] * rZ * uh[ep];
    }
    float* Sout = (which == 1) ? g_S1 : g_S2;
#pragma unroll
    for (int ep = 0; ep < 4; ep++)
        atomicAdd(&Sout[b * 128 + 32 * ep + lane], accS[ep]);
}

__global__ void k_squash(int which, float scale) {
    int b = blockIdx.x, t = threadIdx.x;
    const float* S = (which == 0) ? g_S0 : (which == 1) ? g_S1 : g_S2;
    float s = S[b * 128 + t] * scale;
    float n2 = s * s;
#pragma unroll
    for (int off = 8; off; off >>= 1)
        n2 += __shfl_xor_sync(0xffffffffu, n2, off);
    float nn = sqrtf(n2);
    g_v[b * 128 + t] = (n2 / (1.f + n2)) * s / (nn + 1e-8f);
}

__global__ void k_final(float* __restrict__ out) {
    int b = blockIdx.x, t = threadIdx.x;
    float v = g_v[b * 128 + t];
    float s = v * v;
#pragma unroll
    for (int off = 8; off; off >>= 1)
        s += __shfl_xor_sync(0xffffffffu, s, off);
    if ((t & 15) == 0) out[b * 8 + (t >> 4)] = sqrtf(s);
}

// ---------------------------------------------------------------------------
extern "C" void kernel_launch(void* const* d_in, const int* in_sizes, int n_in,
                              void* d_out, int out_size) {
    const float* x   = (const float*)d_in[0];
    const float* w1  = (const float*)d_in[1];
    const float* b1  = (const float*)d_in[2];
    const float* w2  = (const float*)d_in[3];
    const float* b2  = (const float*)d_in[4];
    const float* w3  = (const float*)d_in[5];
    const float* b3  = (const float*)d_in[6];
    const float* pcw = (const float*)d_in[7];
    const float* pcb = (const float*)d_in[8];
    const float* W   = (const float*)d_in[9];
    float* out = (float*)d_out;

    k_zero_all<<<28800, 256>>>();
    k_conv1<<<20000, 256>>>(x, w1, b1);
    k_prep_w2<<<9216, 256>>>(w2);
    k_prep_w3<<<512, 256>>>(w3);
    k_gemm_mma<0><<<dim3(157, 2), 256>>>(b2);   // conv2
    k_gemm_mma<1><<<dim3(157, 2), 256>>>(b3);   // conv3
    k_caps<<<20000, 128>>>(pcw, pcb, W);
    k_route0<<<dim3(64, 32), 128>>>();
    k_squash<<<32, 128>>>(0, 0.125f);
    k_route_upd<<<dim3(25, 32), 256>>>(1);
    k_squash<<<32, 128>>>(1, 1.f);
    k_route_upd<<<dim3(25, 32), 256>>>(2);
    k_squash<<<32, 128>>>(2, 1.f);
    k_final<<<32, 128>>>(out);
}

// round 5
// speedup vs baseline: 1.6171x; 1.3423x over previous
#include <cuda_runtime.h>
#include <cuda_bf16.h>
#include <math.h>
#include <cstdint>

// ===========================================================================
//   conv1: 256f 6x6 s2 -> (32,256,25,25) ; conv2: 6x6 s1 pad(2,3) -> GEMM
//   M=20000,N=256,K=9216 ; conv3: 1x1 512->256 K=512 ; caps + 3-iter routing
//   All GEMMs: mma.sync bf16 3-term split (hi*hi + hi*lo + lo*hi), fp32 accum.
// ===========================================================================

__device__ __align__(16) __nv_bfloat16 g_xph[32 * 30 * 30 * 256];  // padded conv1, hi
__device__ __align__(16) __nv_bfloat16 g_xpl[32 * 30 * 30 * 256];  // lo
__device__ __align__(16) __nv_bfloat16 g_zch[20000 * 512];         // [conv1|conv2] hi
__device__ __align__(16) __nv_bfloat16 g_zcl[20000 * 512];         // lo
__device__ __align__(16) __nv_bfloat16 g_w2bh[256 * 9216];
__device__ __align__(16) __nv_bfloat16 g_w2bl[256 * 9216];
__device__ __align__(16) __nv_bfloat16 g_w3bh[256 * 512];
__device__ __align__(16) __nv_bfloat16 g_w3bl[256 * 512];
__device__ float g_c3[20000 * 256];
__device__ float g_uhat[32 * 20000 * 128];
__device__ float g_logits[32 * 20000 * 8];
__device__ float g_S0[32 * 128];
__device__ float g_S1[32 * 128];
__device__ float g_S2[32 * 128];
__device__ float g_v[32 * 128];

// ---------------------------------------------------------------------------
__global__ void k_zero_all() {
    int i = blockIdx.x * 256 + threadIdx.x;
    if (i < 3686400) {   // 32*30*30*256 halves / 2
        ((uint32_t*)g_xph)[i] = 0u;
        ((uint32_t*)g_xpl)[i] = 0u;
    }
    if (i < 32 * 20000 * 8) g_logits[i] = 0.f;
    if (i < 32 * 128) { g_S0[i] = 0.f; g_S1[i] = 0.f; g_S2[i] = 0.f; }
}

__global__ void k_conv1(const float* __restrict__ x,
                        const float* __restrict__ w1,
                        const float* __restrict__ b1) {
    __shared__ float xs[36];
    int blk = blockIdx.x;
    int b = blk / 625, p = blk % 625, oh = p / 25, ow = p % 25;
    int t = threadIdx.x;
    if (t < 36) {
        int kh = t / 6, kw = t % 6;
        xs[t] = x[b * 2916 + (2 * oh + kh) * 54 + (2 * ow + kw)];
    }
    __syncthreads();
    float acc = b1[t];
#pragma unroll
    for (int j = 0; j < 36; j++) acc += xs[j] * __ldg(&w1[t * 36 + j]);
    acc = fmaxf(acc, 0.f);
    __nv_bfloat16 h = __float2bfloat16_rn(acc);
    __nv_bfloat16 l = __float2bfloat16_rn(acc - __bfloat162float(h));
    int xi = ((b * 30 + oh + 2) * 30 + (ow + 2)) * 256 + t;
    g_xph[xi] = h; g_xpl[xi] = l;
    int zi = (b * 625 + oh * 25 + ow) * 512 + t;
    g_zch[zi] = h; g_zcl[zi] = l;
}

// conv2 weights (oc,ic,kh,kw) -> split bf16 [oc][khw*256+ic]
__global__ void k_prep_w2s(const float* __restrict__ w2) {
    int i = blockIdx.x * 256 + threadIdx.x;
    if (i < 2359296) {
        int oc = i / 9216, kk = i % 9216;
        int khw = kk >> 8, ic = kk & 255;
        float v = w2[oc * 9216 + ic * 36 + khw];
        __nv_bfloat16 h = __float2bfloat16_rn(v);
        g_w2bh[i] = h;
        g_w2bl[i] = __float2bfloat16_rn(v - __bfloat162float(h));
    }
}
__global__ void k_prep_w3s(const float* __restrict__ w3) {
    int i = blockIdx.x * 256 + threadIdx.x;
    if (i < 131072) {
        float v = w3[i];
        __nv_bfloat16 h = __float2bfloat16_rn(v);
        g_w3bh[i] = h;
        g_w3bl[i] = __float2bfloat16_rn(v - __bfloat162float(h));
    }
}

// ---------------------------------------------------------------------------
// GEMM helpers
// ---------------------------------------------------------------------------
__device__ __forceinline__ uint32_t smem_u32(const void* p) {
    uint32_t a;
    asm("{ .reg .u64 t; cvta.to.shared.u64 t, %1; cvt.u32.u64 %0, t; }" : "=r"(a) : "l"(p));
    return a;
}
__device__ __forceinline__ void cpa16(uint32_t d, const void* g) {
    asm volatile("cp.async.cg.shared.global [%0], [%1], 16;" :: "r"(d), "l"(g) : "memory");
}
#define CP_COMMIT() asm volatile("cp.async.commit_group;" ::: "memory")
#define CP_WAIT(n)  asm volatile("cp.async.wait_group %0;" :: "n"(n) : "memory")

__device__ __forceinline__ void ldsm4(uint32_t& r0, uint32_t& r1, uint32_t& r2, uint32_t& r3,
                                      uint32_t a) {
    asm volatile("ldmatrix.sync.aligned.m8n8.x4.shared.b16 {%0,%1,%2,%3}, [%4];"
                 : "=r"(r0), "=r"(r1), "=r"(r2), "=r"(r3) : "r"(a));
}
__device__ __forceinline__ void mma16816(float& c0, float& c1, float& c2, float& c3,
                                         uint32_t a0, uint32_t a1, uint32_t a2, uint32_t a3,
                                         uint32_t b0, uint32_t b1) {
    asm volatile("mma.sync.aligned.m16n8k16.row.col.f32.bf16.bf16.f32 "
                 "{%0,%1,%2,%3}, {%4,%5,%6,%7}, {%8,%9}, {%0,%1,%2,%3};"
                 : "+f"(c0), "+f"(c1), "+f"(c2), "+f"(c3)
                 : "r"(a0), "r"(a1), "r"(a2), "r"(a3), "r"(b0), "r"(b1));
}

// smem: 3 stages x [Ah | Al | Bh | Bl], each 128 rows x 32 bf16, row stride 80B
#define ROWB   80
#define REGSZ  10240
#define STGSZ  40960
#define SMEM_GEMM (3 * STGSZ)

// MODE 0: conv2 (im2col A from g_xph/g_xpl, K=9216). MODE 1: conv3 (A from g_zch/g_zcl, K=512).
template<int MODE>
__global__ void __launch_bounds__(256) k_gemm2(const float* __restrict__ bias) {
    constexpr int K = (MODE == 0) ? 9216 : 512;
    constexpr int S = K / 32;
    extern __shared__ char sm[];
    __shared__ int s_rowbase[128];
    const uint32_t sbase = smem_u32(sm);
    const int tid = threadIdx.x;
    const int m0 = blockIdx.x * 128, n0 = blockIdx.y * 128;

    if (MODE == 0 && tid < 128) {
        int m = min(m0 + tid, 19999);
        int b = m / 625, p = m % 625, oh = p / 25, ow = p % 25;
        s_rowbase[tid] = ((b * 30 + oh) * 30 + ow) * 256;
    }
    __syncthreads();

    // cp.async region mapping: tid>>6 selects Ah/Al/Bh/Bl
    const int reg = tid >> 6;
    const int t64 = tid & 63;
    const int rrow0 = t64 >> 2;       // + j*16, j=0..7
    const int rkc = t64 & 3;          // 16B chunk in row

    const __nv_bfloat16* WH = (MODE == 0) ? g_w2bh : g_w3bh;
    const __nv_bfloat16* WL = (MODE == 0) ? g_w2bl : g_w3bl;

    auto issue = [&](int s) {
        int k0 = s * 32;
        uint32_t dbase = sbase + (s % 3) * STGSZ + reg * REGSZ;
        if (reg < 2) {
            const __nv_bfloat16* base;
            int aoff = 0;
            if (MODE == 0) {
                base = (reg == 0) ? g_xph : g_xpl;
                int khw = k0 >> 8;
                int kh = khw / 6, kw = khw - kh * 6;
                aoff = (kh * 30 + kw) * 256 + (k0 & 255) + rkc * 8;
            } else {
                base = (reg == 0) ? g_zch : g_zcl;
            }
#pragma unroll
            for (int j = 0; j < 8; j++) {
                int row = rrow0 + j * 16;
                const __nv_bfloat16* src;
                if (MODE == 0) src = base + s_rowbase[row] + aoff;
                else {
                    int m = min(m0 + row, 19999);
                    src = base + m * 512 + k0 + rkc * 8;
                }
                cpa16(dbase + row * ROWB + rkc * 16, src);
            }
        } else {
            const __nv_bfloat16* base = (reg == 2) ? WH : WL;
#pragma unroll
            for (int j = 0; j < 8; j++) {
                int row = rrow0 + j * 16;
                cpa16(dbase + row * ROWB + rkc * 16,
                      base + (size_t)(n0 + row) * K + k0 + rkc * 8);
            }
        }
        CP_COMMIT();
    };

    const int lane = tid & 31, wid = tid >> 5;
    const int wm = (wid & 1) * 64, wn = (wid >> 1) * 32;
    const int grp = lane >> 2, q = lane & 3;
    const int lrow = lane & 15, lk = lane >> 4;

    float acc[4][4][4];
#pragma unroll
    for (int i = 0; i < 4; i++)
#pragma unroll
        for (int j = 0; j < 4; j++)
#pragma unroll
            for (int c = 0; c < 4; c++) acc[i][j][c] = 0.f;

    issue(0);
    issue(1);

    for (int s = 0; s < S; s++) {
        if (s + 2 < S)      { issue(s + 2); CP_WAIT(2); }
        else if (s + 1 < S) { CP_WAIT(1); }
        else                { CP_WAIT(0); }
        __syncthreads();

        uint32_t Ah = sbase + (s % 3) * STGSZ;
        uint32_t Al = Ah + REGSZ, Bh = Ah + 2 * REGSZ, Bl = Ah + 3 * REGSZ;

#pragma unroll
        for (int kk = 0; kk < 2; kk++) {
            uint32_t ah[4][4], al[4][4], bh[4][2], bl[4][2];
            uint32_t ko = kk * 32 + lk * 16;
#pragma unroll
            for (int mi = 0; mi < 4; mi++) {
                uint32_t ro = (uint32_t)(wm + mi * 16 + lrow) * ROWB + ko;
                ldsm4(ah[mi][0], ah[mi][1], ah[mi][2], ah[mi][3], Ah + ro);
                ldsm4(al[mi][0], al[mi][1], al[mi][2], al[mi][3], Al + ro);
            }
#pragma unroll
            for (int p2 = 0; p2 < 2; p2++) {
                uint32_t ro = (uint32_t)(wn + p2 * 16 + lrow) * ROWB + ko;
                uint32_t r0, r1, r2, r3;
                ldsm4(r0, r1, r2, r3, Bh + ro);
                bh[2 * p2][0] = r0; bh[2 * p2][1] = r2;
                bh[2 * p2 + 1][0] = r1; bh[2 * p2 + 1][1] = r3;
                ldsm4(r0, r1, r2, r3, Bl + ro);
                bl[2 * p2][0] = r0; bl[2 * p2][1] = r2;
                bl[2 * p2 + 1][0] = r1; bl[2 * p2 + 1][1] = r3;
            }
#pragma unroll
            for (int mi = 0; mi < 4; mi++)
#pragma unroll
                for (int ni = 0; ni < 4; ni++) {
                    float* c = acc[mi][ni];
                    mma16816(c[0], c[1], c[2], c[3],
                             ah[mi][0], ah[mi][1], ah[mi][2], ah[mi][3],
                             bh[ni][0], bh[ni][1]);
                    mma16816(c[0], c[1], c[2], c[3],
                             ah[mi][0], ah[mi][1], ah[mi][2], ah[mi][3],
                             bl[ni][0], bl[ni][1]);
                    mma16816(c[0], c[1], c[2], c[3],
                             al[mi][0], al[mi][1], al[mi][2], al[mi][3],
                             bh[ni][0], bh[ni][1]);
                }
        }
        __syncthreads();
    }

    // epilogue
#pragma unroll
    for (int mi = 0; mi < 4; mi++) {
#pragma unroll
        for (int ni = 0; ni < 4; ni++) {
            int col = n0 + wn + ni * 8 + 2 * q;
            float bb0 = bias[col], bb1 = bias[col + 1];
            int row0 = m0 + wm + mi * 16 + grp;
            int row1 = row0 + 8;
            float* c = acc[mi][ni];
            if (MODE == 0) {
                if (row0 < 20000) {
                    float v0 = fmaxf(c[0] + bb0, 0.f), v1 = fmaxf(c[1] + bb1, 0.f);
                    __nv_bfloat16 h0 = __float2bfloat16_rn(v0), h1 = __float2bfloat16_rn(v1);
                    __nv_bfloat162 hh; hh.x = h0; hh.y = h1;
                    __nv_bfloat162 ll;
                    ll.x = __float2bfloat16_rn(v0 - __bfloat162float(h0));
                    ll.y = __float2bfloat16_rn(v1 - __bfloat162float(h1));
                    *(__nv_bfloat162*)&g_zch[row0 * 512 + 256 + col] = hh;
                    *(__nv_bfloat162*)&g_zcl[row0 * 512 + 256 + col] = ll;
                }
                if (row1 < 20000) {
                    float v0 = fmaxf(c[2] + bb0, 0.f), v1 = fmaxf(c[3] + bb1, 0.f);
                    __nv_bfloat16 h0 = __float2bfloat16_rn(v0), h1 = __float2bfloat16_rn(v1);
                    __nv_bfloat162 hh; hh.x = h0; hh.y = h1;
                    __nv_bfloat162 ll;
                    ll.x = __float2bfloat16_rn(v0 - __bfloat162float(h0));
                    ll.y = __float2bfloat16_rn(v1 - __bfloat162float(h1));
                    *(__nv_bfloat162*)&g_zch[row1 * 512 + 256 + col] = hh;
                    *(__nv_bfloat162*)&g_zcl[row1 * 512 + 256 + col] = ll;
                }
            } else {
                if (row0 < 20000)
                    *(float2*)&g_c3[row0 * 256 + col] = make_float2(c[0] + bb0, c[1] + bb1);
                if (row1 < 20000)
                    *(float2*)&g_c3[row1 * 256 + col] = make_float2(c[2] + bb0, c[3] + bb1);
            }
        }
    }
}

// ---------------------------------------------------------------------------
// capsules: u = caps @ pc_w^T + pc_b ; u_hat = u @ W^T
// ---------------------------------------------------------------------------
__global__ void k_caps(const float* __restrict__ pcw,
                       const float* __restrict__ pcb,
                       const float* __restrict__ W) {
    __shared__ float s_pcw[64];
    __shared__ float s_pcb[8];
    __shared__ float s_caps[32][8];
    __shared__ float s_u[32][8];
    int n = blockIdx.x;
    int t = threadIdx.x;
    int g = n / 625, hw = n - g * 625;

    if (t < 64) s_pcw[t] = pcw[n * 64 + t];
    if (t < 8)  s_pcb[t] = pcb[n * 8 + t];
#pragma unroll
    for (int r = 0; r < 2; r++) {
        int idx = t + r * 128;
        int b = idx >> 3, i = idx & 7;
        s_caps[b][i] = g_c3[(b * 625 + hw) * 256 + g * 8 + i];
    }
    __syncthreads();
#pragma unroll
    for (int r = 0; r < 2; r++) {
        int idx = t + r * 128;
        int b = idx >> 3, o = idx & 7;
        float u = s_pcb[o];
#pragma unroll
        for (int i = 0; i < 8; i++) u += s_caps[b][i] * s_pcw[o * 8 + i];
        s_u[b][o] = u;
    }
    __syncthreads();
    float wreg[8];
    const float* wp = W + n * 1024 + t * 8;
#pragma unroll
    for (int i = 0; i < 8; i++) wreg[i] = wp[i];
#pragma unroll 4
    for (int b = 0; b < 32; b++) {
        float uh = 0.f;
#pragma unroll
        for (int i = 0; i < 8; i++) uh += s_u[b][i] * wreg[i];
        g_uhat[(b * 20000 + n) * 128 + t] = uh;
    }
}

__global__ void k_route0() {
    int b = blockIdx.y, t = threadIdx.x;
    int n0 = blockIdx.x * 313;
    int n1 = min(20000, n0 + 313);
    float acc = 0.f;
    const float* up = g_uhat + (b * 20000) * 128 + t;
    for (int n = n0; n < n1; n++) acc += up[n * 128];
    atomicAdd(&g_S0[b * 128 + t], acc);
}

__global__ void k_route_upd(int which) {
    int b = blockIdx.y;
    int wid_g = blockIdx.x * 8 + (threadIdx.x >> 5);
    int lane = threadIdx.x & 31;
    int o = lane & 15, eh = lane >> 4;
    int n0 = wid_g * 100, n1 = min(20000, n0 + 100);

    float vv[4];
#pragma unroll
    for (int ep = 0; ep < 4; ep++) vv[ep] = g_v[b * 128 + 32 * ep + lane];

    float accS[4] = {0.f, 0.f, 0.f, 0.f};

    for (int n = n0; n < n1; n++) {
        const float* up = g_uhat + (size_t)(b * 20000 + n) * 128;
        float uh[4], dot[4];
#pragma unroll
        for (int ep = 0; ep < 4; ep++) {
            uh[ep] = up[32 * ep + lane];
            float p = uh[ep] * vv[ep];
#pragma unroll
            for (int off = 8; off; off >>= 1)
                p += __shfl_xor_sync(0xffffffffu, p, off);
            dot[ep] = p;
        }
        size_t lb = (size_t)(b * 20000 + n) * 8;
        float old[4];
        if (o == 0) {
#pragma unroll
            for (int ep = 0; ep < 4; ep++) old[ep] = g_logits[lb + 2 * ep + eh];
        }
        float a[4], m4 = -1e30f;
#pragma unroll
        for (int ep = 0; ep < 4; ep++) {
            float ob = __shfl_sync(0xffffffffu, old[ep], lane & 16);
            a[ep] = ob + dot[ep];
            m4 = fmaxf(m4, a[ep]);
        }
        if (o == 0) {
#pragma unroll
            for (int ep = 0; ep < 4; ep++) g_logits[lb + 2 * ep + eh] = a[ep];
        }
        float amax = fmaxf(m4, __shfl_xor_sync(0xffffffffu, m4, 16));
        float ex[4], s4 = 0.f;
#pragma unroll
        for (int ep = 0; ep < 4; ep++) { ex[ep] = __expf(a[ep] - amax); s4 += ex[ep]; }
        float Z = s4 + __shfl_xor_sync(0xffffffffu, s4, 16);
        float rZ = 1.f / Z;
#pragma unroll
        for (int ep = 0; ep < 4; ep++) accS[ep] += ex[ep] * rZ * uh[ep];
    }
    float* Sout = (which == 1) ? g_S1 : g_S2;
#pragma unroll
    for (int ep = 0; ep < 4; ep++)
        atomicAdd(&Sout[b * 128 + 32 * ep + lane], accS[ep]);
}

__global__ void k_squash(int which, float scale) {
    int b = blockIdx.x, t = threadIdx.x;
    const float* S = (which == 0) ? g_S0 : (which == 1) ? g_S1 : g_S2;
    float s = S[b * 128 + t] * scale;
    float n2 = s * s;
#pragma unroll
    for (int off = 8; off; off >>= 1)
        n2 += __shfl_xor_sync(0xffffffffu, n2, off);
    float nn = sqrtf(n2);
    g_v[b * 128 + t] = (n2 / (1.f + n2)) * s / (nn + 1e-8f);
}

__global__ void k_final(float* __restrict__ out) {
    int b = blockIdx.x, t = threadIdx.x;
    float v = g_v[b * 128 + t];
    float s = v * v;
#pragma unroll
    for (int off = 8; off; off >>= 1)
        s += __shfl_xor_sync(0xffffffffu, s, off);
    if ((t & 15) == 0) out[b * 8 + (t >> 4)] = sqrtf(s);
}

// ===========================================================================
extern "C" void kernel_launch(void* const* d_in, const int* in_sizes, int n_in,
                              void* d_out, int out_size) {
    const float* x   = (const float*)d_in[0];
    const float* w1  = (const float*)d_in[1];
    const float* b1  = (const float*)d_in[2];
    const float* w2  = (const float*)d_in[3];
    const float* b2  = (const float*)d_in[4];
    const float* w3  = (const float*)d_in[5];
    const float* b3  = (const float*)d_in[6];
    const float* pcw = (const float*)d_in[7];
    const float* pcb = (const float*)d_in[8];
    const float* W   = (const float*)d_in[9];
    float* out = (float*)d_out;

    cudaFuncSetAttribute(k_gemm2<0>, cudaFuncAttributeMaxDynamicSharedMemorySize, SMEM_GEMM);
    cudaFuncSetAttribute(k_gemm2<1>, cudaFuncAttributeMaxDynamicSharedMemorySize, SMEM_GEMM);

    k_zero_all<<<28800, 256>>>();
    k_conv1<<<20000, 256>>>(x, w1, b1);
    k_prep_w2s<<<9216, 256>>>(w2);
    k_gemm2<0><<<dim3(157, 2), 256, SMEM_GEMM>>>(b2);   // conv2 (profiled slot)
    k_prep_w3s<<<512, 256>>>(w3);
    k_gemm2<1><<<dim3(157, 2), 256, SMEM_GEMM>>>(b3);   // conv3
    k_caps<<<20000, 128>>>(pcw, pcb, W);
    k_route0<<<dim3(64, 32), 128>>>();
    k_squash<<<32, 128>>>(0, 0.125f);
    k_route_upd<<<dim3(25, 32), 256>>>(1);
    k_squash<<<32, 128>>>(1, 1.f);
    k_route_upd<<<dim3(25, 32), 256>>>(2);
    k_squash<<<32, 128>>>(2, 1.f);
    k_final<<<32, 128>>>(out);
}

// round 6
// speedup vs baseline: 1.9541x; 1.2084x over previous
#include <cuda_runtime.h>
#include <cuda_bf16.h>
#include <math.h>
#include <cstdint>

// ===========================================================================
//   conv1: 256f 6x6 s2 -> (32,256,25,25) ; conv2: 6x6 s1 pad(2,3) -> GEMM
//   M=20000,N=256,K=9216 ; conv3: 1x1 512->256 K=512 ; caps + 3-iter routing
//   GEMMs: mma.sync bf16 3-term split (hi*hi + hi*lo + lo*hi), fp32 accum.
// ===========================================================================

__device__ __align__(16) __nv_bfloat16 g_xph[32 * 30 * 30 * 256];
__device__ __align__(16) __nv_bfloat16 g_xpl[32 * 30 * 30 * 256];
__device__ __align__(16) __nv_bfloat16 g_zch[20000 * 512];
__device__ __align__(16) __nv_bfloat16 g_zcl[20000 * 512];
__device__ __align__(16) __nv_bfloat16 g_w2bh[256 * 9216];
__device__ __align__(16) __nv_bfloat16 g_w2bl[256 * 9216];
__device__ __align__(16) __nv_bfloat16 g_w3bh[256 * 512];
__device__ __align__(16) __nv_bfloat16 g_w3bl[256 * 512];
__device__ float g_c3[20000 * 256];
__device__ float g_uhat[32 * 20000 * 128];
__device__ float g_logits[32 * 20000 * 8];
__device__ float g_S0[32 * 128];
__device__ float g_S1[32 * 128];
__device__ float g_S2[32 * 128];
__device__ float g_v[32 * 128];

// ---------------------------------------------------------------------------
__global__ void k_zero_all() {
    int i = blockIdx.x * 256 + threadIdx.x;
    if (i < 3686400) {
        ((uint32_t*)g_xph)[i] = 0u;
        ((uint32_t*)g_xpl)[i] = 0u;
    }
    if (i < 32 * 20000 * 8) g_logits[i] = 0.f;
    if (i < 32 * 128) { g_S0[i] = 0.f; g_S1[i] = 0.f; g_S2[i] = 0.f; }
}

__global__ void k_conv1(const float* __restrict__ x,
                        const float* __restrict__ w1,
                        const float* __restrict__ b1) {
    __shared__ float xs[36];
    int blk = blockIdx.x;
    int b = blk / 625, p = blk % 625, oh = p / 25, ow = p % 25;
    int t = threadIdx.x;
    if (t < 36) {
        int kh = t / 6, kw = t % 6;
        xs[t] = x[b * 2916 + (2 * oh + kh) * 54 + (2 * ow + kw)];
    }
    __syncthreads();
    float acc = b1[t];
#pragma unroll
    for (int j = 0; j < 36; j++) acc += xs[j] * __ldg(&w1[t * 36 + j]);
    acc = fmaxf(acc, 0.f);
    __nv_bfloat16 h = __float2bfloat16_rn(acc);
    __nv_bfloat16 l = __float2bfloat16_rn(acc - __bfloat162float(h));
    int xi = ((b * 30 + oh + 2) * 30 + (ow + 2)) * 256 + t;
    g_xph[xi] = h; g_xpl[xi] = l;
    int zi = (b * 625 + oh * 25 + ow) * 512 + t;
    g_zch[zi] = h; g_zcl[zi] = l;
}

// conv2 weights (oc,ic,kh,kw) -> split bf16 [oc][khw*256+ic], coalesced both ways
__global__ void k_prep_w2s(const float* __restrict__ w2) {
    __shared__ float s[256 * 37];       // [ic][khw] padded
    int oc = blockIdx.x;
    int t = threadIdx.x;
    for (int j = 0; j < 36; j++) {
        int idx = t + 256 * j;          // = ic*36 + khw
        int ic = idx / 36, khw = idx % 36;
        s[ic * 37 + khw] = w2[oc * 9216 + idx];
    }
    __syncthreads();
    for (int j = 0; j < 36; j++) {
        int o = t + 256 * j;            // = khw*256 + ic
        int khw = o >> 8, ic = o & 255;
        float v = s[ic * 37 + khw];
        __nv_bfloat16 h = __float2bfloat16_rn(v);
        g_w2bh[oc * 9216 + o] = h;
        g_w2bl[oc * 9216 + o] = __float2bfloat16_rn(v - __bfloat162float(h));
    }
}
__global__ void k_prep_w3s(const float* __restrict__ w3) {
    int i = blockIdx.x * 256 + threadIdx.x;
    if (i < 131072) {
        float v = w3[i];
        __nv_bfloat16 h = __float2bfloat16_rn(v);
        g_w3bh[i] = h;
        g_w3bl[i] = __float2bfloat16_rn(v - __bfloat162float(h));
    }
}

// ---------------------------------------------------------------------------
// GEMM helpers
// ---------------------------------------------------------------------------
__device__ __forceinline__ uint32_t smem_u32(const void* p) {
    uint32_t a;
    asm("{ .reg .u64 t; cvta.to.shared.u64 t, %1; cvt.u32.u64 %0, t; }" : "=r"(a) : "l"(p));
    return a;
}
__device__ __forceinline__ void cpa16(uint32_t d, const void* g) {
    asm volatile("cp.async.cg.shared.global [%0], [%1], 16;" :: "r"(d), "l"(g) : "memory");
}
#define CP_COMMIT() asm volatile("cp.async.commit_group;" ::: "memory")
#define CP_WAIT(n)  asm volatile("cp.async.wait_group %0;" :: "n"(n) : "memory")

__device__ __forceinline__ void ldsm4(uint32_t& r0, uint32_t& r1, uint32_t& r2, uint32_t& r3,
                                      uint32_t a) {
    asm volatile("ldmatrix.sync.aligned.m8n8.x4.shared.b16 {%0,%1,%2,%3}, [%4];"
                 : "=r"(r0), "=r"(r1), "=r"(r2), "=r"(r3) : "r"(a));
}
__device__ __forceinline__ void mma16816(float& c0, float& c1, float& c2, float& c3,
                                         uint32_t a0, uint32_t a1, uint32_t a2, uint32_t a3,
                                         uint32_t b0, uint32_t b1) {
    asm volatile("mma.sync.aligned.m16n8k16.row.col.f32.bf16.bf16.f32 "
                 "{%0,%1,%2,%3}, {%4,%5,%6,%7}, {%8,%9}, {%0,%1,%2,%3};"
                 : "+f"(c0), "+f"(c1), "+f"(c2), "+f"(c3)
                 : "r"(a0), "r"(a1), "r"(a2), "r"(a3), "r"(b0), "r"(b1));
}

// swizzled 64B-row addressing: 4 chunks of 16B per row, chunk ^= (row>>1)&3.
// Conflict-free for both cp.async 16B stores and ldmatrix reads.
__device__ __forceinline__ uint32_t swaddr(uint32_t region, int row, int chunk) {
    return region + (uint32_t)row * 64u + (uint32_t)((chunk ^ ((row >> 1) & 3)) << 4);
}

// smem: 3 stages x [Ah | Al | Bh | Bl], each 128 rows x 32 bf16 (64B rows)
#define REGSZ  8192
#define STGSZ  32768
#define SMEM_GEMM (3 * STGSZ)

template<int MODE>
__global__ void __launch_bounds__(256, 2) k_gemm2(const float* __restrict__ bias) {
    constexpr int K = (MODE == 0) ? 9216 : 512;
    constexpr int S = K / 32;
    extern __shared__ char sm[];
    __shared__ int s_rowbase[128];
    const uint32_t sbase = smem_u32(sm);
    const int tid = threadIdx.x;
    const int m0 = blockIdx.x * 128, n0 = blockIdx.y * 128;

    if (MODE == 0 && tid < 128) {
        int m = min(m0 + tid, 19999);
        int b = m / 625, p = m % 625, oh = p / 25, ow = p % 25;
        s_rowbase[tid] = ((b * 30 + oh) * 30 + ow) * 256;
    }
    __syncthreads();

    const int reg = tid >> 6;          // 0:Ah 1:Al 2:Bh 3:Bl
    const int t64 = tid & 63;
    const int rrow0 = t64 >> 2;        // + j*16
    const int rkc = t64 & 3;           // 16B chunk in row

    const __nv_bfloat16* WH = (MODE == 0) ? g_w2bh : g_w3bh;
    const __nv_bfloat16* WL = (MODE == 0) ? g_w2bl : g_w3bl;

    auto issue = [&](int s) {
        int k0 = s * 32;
        uint32_t dbase = sbase + (s % 3) * STGSZ + reg * REGSZ;
        if (reg < 2) {
            const __nv_bfloat16* base;
            int aoff = 0;
            if (MODE == 0) {
                base = (reg == 0) ? g_xph : g_xpl;
                int khw = k0 >> 8;
                int kh = khw / 6, kw = khw - kh * 6;
                aoff = (kh * 30 + kw) * 256 + (k0 & 255) + rkc * 8;
            } else {
                base = (reg == 0) ? g_zch : g_zcl;
            }
#pragma unroll
            for (int j = 0; j < 8; j++) {
                int row = rrow0 + j * 16;
                const __nv_bfloat16* src;
                if (MODE == 0) src = base + s_rowbase[row] + aoff;
                else {
                    int m = min(m0 + row, 19999);
                    src = base + m * 512 + k0 + rkc * 8;
                }
                cpa16(swaddr(dbase, row, rkc), src);
            }
        } else {
            const __nv_bfloat16* base = (reg == 2) ? WH : WL;
#pragma unroll
            for (int j = 0; j < 8; j++) {
                int row = rrow0 + j * 16;
                cpa16(swaddr(dbase, row, rkc),
                      base + (size_t)(n0 + row) * K + k0 + rkc * 8);
            }
        }
        CP_COMMIT();
    };

    const int lane = tid & 31, wid = tid >> 5;
    const int wm = (wid & 1) * 64, wn = (wid >> 1) * 32;
    const int grp = lane >> 2, q = lane & 3;
    const int lrow = lane & 15, lk = lane >> 4;

    float acc[4][4][4];
#pragma unroll
    for (int i = 0; i < 4; i++)
#pragma unroll
        for (int j = 0; j < 4; j++)
#pragma unroll
            for (int c = 0; c < 4; c++) acc[i][j][c] = 0.f;

    issue(0);
    issue(1);

    for (int s = 0; s < S; s++) {
        if (s + 2 < S)      { issue(s + 2); CP_WAIT(2); }
        else if (s + 1 < S) { CP_WAIT(1); }
        else                { CP_WAIT(0); }
        __syncthreads();

        uint32_t Ah = sbase + (s % 3) * STGSZ;
        uint32_t Al = Ah + REGSZ, Bh = Ah + 2 * REGSZ, Bl = Ah + 3 * REGSZ;

#pragma unroll
        for (int kk = 0; kk < 2; kk++) {
            uint32_t ah[4][4], al[4][4], bh[4][2], bl[4][2];
            int ckc = kk * 2 + lk;     // chunk index 0..3
#pragma unroll
            for (int mi = 0; mi < 4; mi++) {
                int row = wm + mi * 16 + lrow;
                ldsm4(ah[mi][0], ah[mi][1], ah[mi][2], ah[mi][3], swaddr(Ah, row, ckc));
                ldsm4(al[mi][0], al[mi][1], al[mi][2], al[mi][3], swaddr(Al, row, ckc));
            }
#pragma unroll
            for (int p2 = 0; p2 < 2; p2++) {
                int row = wn + p2 * 16 + lrow;
                uint32_t r0, r1, r2, r3;
                ldsm4(r0, r1, r2, r3, swaddr(Bh, row, ckc));
                bh[2 * p2][0] = r0; bh[2 * p2][1] = r2;
                bh[2 * p2 + 1][0] = r1; bh[2 * p2 + 1][1] = r3;
                ldsm4(r0, r1, r2, r3, swaddr(Bl, row, ckc));
                bl[2 * p2][0] = r0; bl[2 * p2][1] = r2;
                bl[2 * p2 + 1][0] = r1; bl[2 * p2 + 1][1] = r3;
            }
#pragma unroll
            for (int mi = 0; mi < 4; mi++)
#pragma unroll
                for (int ni = 0; ni < 4; ni++) {
                    float* c = acc[mi][ni];
                    mma16816(c[0], c[1], c[2], c[3],
                             ah[mi][0], ah[mi][1], ah[mi][2], ah[mi][3],
                             bh[ni][0], bh[ni][1]);
                    mma16816(c[0], c[1], c[2], c[3],
                             ah[mi][0], ah[mi][1], ah[mi][2], ah[mi][3],
                             bl[ni][0], bl[ni][1]);
                    mma16816(c[0], c[1], c[2], c[3],
                             al[mi][0], al[mi][1], al[mi][2], al[mi][3],
                             bh[ni][0], bh[ni][1]);
                }
        }
        __syncthreads();
    }

    // epilogue
#pragma unroll
    for (int mi = 0; mi < 4; mi++) {
#pragma unroll
        for (int ni = 0; ni < 4; ni++) {
            int col = n0 + wn + ni * 8 + 2 * q;
            float bb0 = bias[col], bb1 = bias[col + 1];
            int row0 = m0 + wm + mi * 16 + grp;
            int row1 = row0 + 8;
            float* c = acc[mi][ni];
            if (MODE == 0) {
                if (row0 < 20000) {
                    float v0 = fmaxf(c[0] + bb0, 0.f), v1 = fmaxf(c[1] + bb1, 0.f);
                    __nv_bfloat16 h0 = __float2bfloat16_rn(v0), h1 = __float2bfloat16_rn(v1);
                    __nv_bfloat162 hh; hh.x = h0; hh.y = h1;
                    __nv_bfloat162 ll;
                    ll.x = __float2bfloat16_rn(v0 - __bfloat162float(h0));
                    ll.y = __float2bfloat16_rn(v1 - __bfloat162float(h1));
                    *(__nv_bfloat162*)&g_zch[row0 * 512 + 256 + col] = hh;
                    *(__nv_bfloat162*)&g_zcl[row0 * 512 + 256 + col] = ll;
                }
                if (row1 < 20000) {
                    float v0 = fmaxf(c[2] + bb0, 0.f), v1 = fmaxf(c[3] + bb1, 0.f);
                    __nv_bfloat16 h0 = __float2bfloat16_rn(v0), h1 = __float2bfloat16_rn(v1);
                    __nv_bfloat162 hh; hh.x = h0; hh.y = h1;
                    __nv_bfloat162 ll;
                    ll.x = __float2bfloat16_rn(v0 - __bfloat162float(h0));
                    ll.y = __float2bfloat16_rn(v1 - __bfloat162float(h1));
                    *(__nv_bfloat162*)&g_zch[row1 * 512 + 256 + col] = hh;
                    *(__nv_bfloat162*)&g_zcl[row1 * 512 + 256 + col] = ll;
                }
            } else {
                if (row0 < 20000)
                    *(float2*)&g_c3[row0 * 256 + col] = make_float2(c[0] + bb0, c[1] + bb1);
                if (row1 < 20000)
                    *(float2*)&g_c3[row1 * 256 + col] = make_float2(c[2] + bb0, c[3] + bb1);
            }
        }
    }
}

// ---------------------------------------------------------------------------
// capsules: u = caps @ pc_w^T + pc_b ; u_hat = u @ W^T
// ---------------------------------------------------------------------------
__global__ void k_caps(const float* __restrict__ pcw,
                       const float* __restrict__ pcb,
                       const float* __restrict__ W) {
    __shared__ float s_pcw[64];
    __shared__ float s_pcb[8];
    __shared__ float s_caps[32][8];
    __shared__ float s_u[32][8];
    int n = blockIdx.x;
    int t = threadIdx.x;
    int g = n / 625, hw = n - g * 625;

    if (t < 64) s_pcw[t] = pcw[n * 64 + t];
    if (t < 8)  s_pcb[t] = pcb[n * 8 + t];
#pragma unroll
    for (int r = 0; r < 2; r++) {
        int idx = t + r * 128;
        int b = idx >> 3, i = idx & 7;
        s_caps[b][i] = g_c3[(b * 625 + hw) * 256 + g * 8 + i];
    }
    __syncthreads();
#pragma unroll
    for (int r = 0; r < 2; r++) {
        int idx = t + r * 128;
        int b = idx >> 3, o = idx & 7;
        float u = s_pcb[o];
#pragma unroll
        for (int i = 0; i < 8; i++) u += s_caps[b][i] * s_pcw[o * 8 + i];
        s_u[b][o] = u;
    }
    __syncthreads();
    float wreg[8];
    const float* wp = W + n * 1024 + t * 8;
#pragma unroll
    for (int i = 0; i < 8; i++) wreg[i] = wp[i];
#pragma unroll 4
    for (int b = 0; b < 32; b++) {
        float uh = 0.f;
#pragma unroll
        for (int i = 0; i < 8; i++) uh += s_u[b][i] * wreg[i];
        g_uhat[(b * 20000 + n) * 128 + t] = uh;
    }
}

__global__ void k_route0() {
    int b = blockIdx.y, t = threadIdx.x;
    int n0 = blockIdx.x * 313;
    int n1 = min(20000, n0 + 313);
    float acc = 0.f;
    const float* up = g_uhat + (b * 20000) * 128 + t;
    for (int n = n0; n < n1; n++) acc += up[n * 128];
    atomicAdd(&g_S0[b * 128 + t], acc);
}

__global__ void k_route_upd(int which) {
    int b = blockIdx.y;
    int wid_g = blockIdx.x * 8 + (threadIdx.x >> 5);
    int lane = threadIdx.x & 31;
    int o = lane & 15, eh = lane >> 4;
    int n0 = wid_g * 100, n1 = min(20000, n0 + 100);

    float vv[4];
#pragma unroll
    for (int ep = 0; ep < 4; ep++) vv[ep] = g_v[b * 128 + 32 * ep + lane];

    float accS[4] = {0.f, 0.f, 0.f, 0.f};

    for (int n = n0; n < n1; n++) {
        const float* up = g_uhat + (size_t)(b * 20000 + n) * 128;
        float uh[4], dot[4];
#pragma unroll
        for (int ep = 0; ep < 4; ep++) {
            uh[ep] = up[32 * ep + lane];
            float p = uh[ep] * vv[ep];
#pragma unroll
            for (int off = 8; off; off >>= 1)
                p += __shfl_xor_sync(0xffffffffu, p, off);
            dot[ep] = p;
        }
        size_t lb = (size_t)(b * 20000 + n) * 8;
        float old[4];
        if (o == 0) {
#pragma unroll
            for (int ep = 0; ep < 4; ep++) old[ep] = g_logits[lb + 2 * ep + eh];
        }
        float a[4], m4 = -1e30f;
#pragma unroll
        for (int ep = 0; ep < 4; ep++) {
            float ob = __shfl_sync(0xffffffffu, old[ep], lane & 16);
            a[ep] = ob + dot[ep];
            m4 = fmaxf(m4, a[ep]);
        }
        if (o == 0) {
#pragma unroll
            for (int ep = 0; ep < 4; ep++) g_logits[lb + 2 * ep + eh] = a[ep];
        }
        float amax = fmaxf(m4, __shfl_xor_sync(0xffffffffu, m4, 16));
        float ex[4], s4 = 0.f;
#pragma unroll
        for (int ep = 0; ep < 4; ep++) { ex[ep] = __expf(a[ep] - amax); s4 += ex[ep]; }
        float Z = s4 + __shfl_xor_sync(0xffffffffu, s4, 16);
        float rZ = 1.f / Z;
#pragma unroll
        for (int ep = 0; ep < 4; ep++) accS[ep] += ex[ep] * rZ * uh[ep];
    }
    float* Sout = (which == 1) ? g_S1 : g_S2;
#pragma unroll
    for (int ep = 0; ep < 4; ep++)
        atomicAdd(&Sout[b * 128 + 32 * ep + lane], accS[ep]);
}

__global__ void k_squash(int which, float scale) {
    int b = blockIdx.x, t = threadIdx.x;
    const float* S = (which == 0) ? g_S0 : (which == 1) ? g_S1 : g_S2;
    float s = S[b * 128 + t] * scale;
    float n2 = s * s;
#pragma unroll
    for (int off = 8; off; off >>= 1)
        n2 += __shfl_xor_sync(0xffffffffu, n2, off);
    float nn = sqrtf(n2);
    g_v[b * 128 + t] = (n2 / (1.f + n2)) * s / (nn + 1e-8f);
}

__global__ void k_final(float* __restrict__ out) {
    int b = blockIdx.x, t = threadIdx.x;
    float v = g_v[b * 128 + t];
    float s = v * v;
#pragma unroll
    for (int off = 8; off; off >>= 1)
        s += __shfl_xor_sync(0xffffffffu, s, off);
    if ((t & 15) == 0) out[b * 8 + (t >> 4)] = sqrtf(s);
}

// ===========================================================================
extern "C" void kernel_launch(void* const* d_in, const int* in_sizes, int n_in,
                              void* d_out, int out_size) {
    const float* x   = (const float*)d_in[0];
    const float* w1  = (const float*)d_in[1];
    const float* b1  = (const float*)d_in[2];
    const float* w2  = (const float*)d_in[3];
    const float* b2  = (const float*)d_in[4];
    const float* w3  = (const float*)d_in[5];
    const float* b3  = (const float*)d_in[6];
    const float* pcw = (const float*)d_in[7];
    const float* pcb = (const float*)d_in[8];
    const float* W   = (const float*)d_in[9];
    float* out = (float*)d_out;

    cudaFuncSetAttribute(k_gemm2<0>, cudaFuncAttributeMaxDynamicSharedMemorySize, SMEM_GEMM);
    cudaFuncSetAttribute(k_gemm2<1>, cudaFuncAttributeMaxDynamicSharedMemorySize, SMEM_GEMM);

    k_zero_all<<<28800, 256>>>();
    k_conv1<<<20000, 256>>>(x, w1, b1);
    k_prep_w2s<<<256, 256>>>(w2);
    k_gemm2<0><<<dim3(157, 2), 256, SMEM_GEMM>>>(b2);   // conv2 (profiled slot)
    k_prep_w3s<<<512, 256>>>(w3);
    k_gemm2<1><<<dim3(157, 2), 256, SMEM_GEMM>>>(b3);   // conv3
    k_caps<<<20000, 128>>>(pcw, pcb, W);
    k_route0<<<dim3(64, 32), 128>>>();
    k_squash<<<32, 128>>>(0, 0.125f);
    k_route_upd<<<dim3(25, 32), 256>>>(1);
    k_squash<<<32, 128>>>(1, 1.f);
    k_route_upd<<<dim3(25, 32), 256>>>(2);
    k_squash<<<32, 128>>>(2, 1.f);
    k_final<<<32, 128>>>(out);
}

// round 7
// speedup vs baseline: 1.9894x; 1.0181x over previous
#include <cuda_runtime.h>
#include <cuda_bf16.h>
#include <math.h>
#include <cstdint>

// ===========================================================================
//   conv1 -> conv2 (implicit GEMM M=20000,N=256,K=9216, bf16 3-split HMMA)
//   conv3 (K=512) -> u (20000,32,8) -> routing with on-the-fly u_hat
// ===========================================================================

__device__ __align__(16) __nv_bfloat16 g_xph[32 * 30 * 30 * 256];
__device__ __align__(16) __nv_bfloat16 g_xpl[32 * 30 * 30 * 256];
__device__ __align__(16) __nv_bfloat16 g_zch[20000 * 512];
__device__ __align__(16) __nv_bfloat16 g_zcl[20000 * 512];
__device__ __align__(16) __nv_bfloat16 g_w2bh[256 * 9216];
__device__ __align__(16) __nv_bfloat16 g_w2bl[256 * 9216];
__device__ __align__(16) __nv_bfloat16 g_w3bh[256 * 512];
__device__ __align__(16) __nv_bfloat16 g_w3bl[256 * 512];
__device__ float g_c3[20000 * 256];
__device__ float g_u[20000 * 256];       // u[n][b][o]  (n-major)
__device__ float g_S0[32 * 128];
__device__ float g_S1[32 * 128];
__device__ float g_S2[32 * 128];
__device__ float g_v0[32 * 128];
__device__ float g_v1[32 * 128];
__device__ float g_v2[32 * 128];

// ---------------------------------------------------------------------------
__global__ void k_zero_all() {
    int i = blockIdx.x * 256 + threadIdx.x;
    if (i < 3686400) {
        ((uint32_t*)g_xph)[i] = 0u;
        ((uint32_t*)g_xpl)[i] = 0u;
    }
    if (i < 32 * 128) { g_S0[i] = 0.f; g_S1[i] = 0.f; g_S2[i] = 0.f; }
}

__global__ void k_conv1(const float* __restrict__ x,
                        const float* __restrict__ w1,
                        const float* __restrict__ b1) {
    __shared__ float xs[36];
    int blk = blockIdx.x;
    int b = blk / 625, p = blk % 625, oh = p / 25, ow = p % 25;
    int t = threadIdx.x;
    if (t < 36) {
        int kh = t / 6, kw = t % 6;
        xs[t] = x[b * 2916 + (2 * oh + kh) * 54 + (2 * ow + kw)];
    }
    __syncthreads();
    float acc = b1[t];
#pragma unroll
    for (int j = 0; j < 36; j++) acc += xs[j] * __ldg(&w1[t * 36 + j]);
    acc = fmaxf(acc, 0.f);
    __nv_bfloat16 h = __float2bfloat16_rn(acc);
    __nv_bfloat16 l = __float2bfloat16_rn(acc - __bfloat162float(h));
    int xi = ((b * 30 + oh + 2) * 30 + (ow + 2)) * 256 + t;
    g_xph[xi] = h; g_xpl[xi] = l;
    int zi = (b * 625 + oh * 25 + ow) * 512 + t;
    g_zch[zi] = h; g_zcl[zi] = l;
}

__global__ void k_prep_w2s(const float* __restrict__ w2) {
    __shared__ float s[256 * 37];
    int oc = blockIdx.x;
    int t = threadIdx.x;
    for (int j = 0; j < 36; j++) {
        int idx = t + 256 * j;
        int ic = idx / 36, khw = idx % 36;
        s[ic * 37 + khw] = w2[oc * 9216 + idx];
    }
    __syncthreads();
    for (int j = 0; j < 36; j++) {
        int o = t + 256 * j;
        int khw = o >> 8, ic = o & 255;
        float v = s[ic * 37 + khw];
        __nv_bfloat16 h = __float2bfloat16_rn(v);
        g_w2bh[oc * 9216 + o] = h;
        g_w2bl[oc * 9216 + o] = __float2bfloat16_rn(v - __bfloat162float(h));
    }
}
__global__ void k_prep_w3s(const float* __restrict__ w3) {
    int i = blockIdx.x * 256 + threadIdx.x;
    if (i < 131072) {
        float v = w3[i];
        __nv_bfloat16 h = __float2bfloat16_rn(v);
        g_w3bh[i] = h;
        g_w3bl[i] = __float2bfloat16_rn(v - __bfloat162float(h));
    }
}

// ---------------------------------------------------------------------------
// GEMM helpers
// ---------------------------------------------------------------------------
__device__ __forceinline__ uint32_t smem_u32(const void* p) {
    uint32_t a;
    asm("{ .reg .u64 t; cvta.to.shared.u64 t, %1; cvt.u32.u64 %0, t; }" : "=r"(a) : "l"(p));
    return a;
}
__device__ __forceinline__ void cpa16(uint32_t d, const void* g) {
    asm volatile("cp.async.cg.shared.global [%0], [%1], 16;" :: "r"(d), "l"(g) : "memory");
}
#define CP_COMMIT() asm volatile("cp.async.commit_group;" ::: "memory")
#define CP_WAIT(n)  asm volatile("cp.async.wait_group %0;" :: "n"(n) : "memory")

__device__ __forceinline__ void ldsm4(uint32_t& r0, uint32_t& r1, uint32_t& r2, uint32_t& r3,
                                      uint32_t a) {
    asm volatile("ldmatrix.sync.aligned.m8n8.x4.shared.b16 {%0,%1,%2,%3}, [%4];"
                 : "=r"(r0), "=r"(r1), "=r"(r2), "=r"(r3) : "r"(a));
}
__device__ __forceinline__ void mma16816(float& c0, float& c1, float& c2, float& c3,
                                         uint32_t a0, uint32_t a1, uint32_t a2, uint32_t a3,
                                         uint32_t b0, uint32_t b1) {
    asm volatile("mma.sync.aligned.m16n8k16.row.col.f32.bf16.bf16.f32 "
                 "{%0,%1,%2,%3}, {%4,%5,%6,%7}, {%8,%9}, {%0,%1,%2,%3};"
                 : "+f"(c0), "+f"(c1), "+f"(c2), "+f"(c3)
                 : "r"(a0), "r"(a1), "r"(a2), "r"(a3), "r"(b0), "r"(b1));
}

__device__ __forceinline__ uint32_t swaddr(uint32_t region, int row, int chunk) {
    return region + (uint32_t)row * 64u + (uint32_t)((chunk ^ ((row >> 1) & 3)) << 4);
}

#define REGSZ  8192
#define STGSZ  32768
#define SMEM_GEMM (3 * STGSZ)

template<int MODE>
__global__ void __launch_bounds__(256, 2) k_gemm2(const float* __restrict__ bias) {
    constexpr int K = (MODE == 0) ? 9216 : 512;
    constexpr int S = K / 32;
    extern __shared__ char sm[];
    __shared__ int s_rowbase[128];
    const uint32_t sbase = smem_u32(sm);
    const int tid = threadIdx.x;
    const int m0 = blockIdx.x * 128, n0 = blockIdx.y * 128;

    if (MODE == 0 && tid < 128) {
        int m = min(m0 + tid, 19999);
        int b = m / 625, p = m % 625, oh = p / 25, ow = p % 25;
        s_rowbase[tid] = ((b * 30 + oh) * 30 + ow) * 256;
    }
    __syncthreads();

    const int reg = tid >> 6;
    const int t64 = tid & 63;
    const int rrow0 = t64 >> 2;
    const int rkc = t64 & 3;

    const __nv_bfloat16* WH = (MODE == 0) ? g_w2bh : g_w3bh;
    const __nv_bfloat16* WL = (MODE == 0) ? g_w2bl : g_w3bl;

    auto issue = [&](int s) {
        int k0 = s * 32;
        uint32_t dbase = sbase + (s % 3) * STGSZ + reg * REGSZ;
        if (reg < 2) {
            const __nv_bfloat16* base;
            int aoff = 0;
            if (MODE == 0) {
                base = (reg == 0) ? g_xph : g_xpl;
                int khw = k0 >> 8;
                int kh = khw / 6, kw = khw - kh * 6;
                aoff = (kh * 30 + kw) * 256 + (k0 & 255) + rkc * 8;
            } else {
                base = (reg == 0) ? g_zch : g_zcl;
            }
#pragma unroll
            for (int j = 0; j < 8; j++) {
                int row = rrow0 + j * 16;
                const __nv_bfloat16* src;
                if (MODE == 0) src = base + s_rowbase[row] + aoff;
                else {
                    int m = min(m0 + row, 19999);
                    src = base + m * 512 + k0 + rkc * 8;
                }
                cpa16(swaddr(dbase, row, rkc), src);
            }
        } else {
            const __nv_bfloat16* base = (reg == 2) ? WH : WL;
#pragma unroll
            for (int j = 0; j < 8; j++) {
                int row = rrow0 + j * 16;
                cpa16(swaddr(dbase, row, rkc),
                      base + (size_t)(n0 + row) * K + k0 + rkc * 8);
            }
        }
        CP_COMMIT();
    };

    const int lane = tid & 31, wid = tid >> 5;
    const int wm = (wid & 1) * 64, wn = (wid >> 1) * 32;
    const int grp = lane >> 2, q = lane & 3;
    const int lrow = lane & 15, lk = lane >> 4;

    float acc[4][4][4];
#pragma unroll
    for (int i = 0; i < 4; i++)
#pragma unroll
        for (int j = 0; j < 4; j++)
#pragma unroll
            for (int c = 0; c < 4; c++) acc[i][j][c] = 0.f;

    issue(0);
    issue(1);

    for (int s = 0; s < S; s++) {
        if (s < S - 1) CP_WAIT(1); else CP_WAIT(0);
        __syncthreads();
        if (s + 2 < S) issue(s + 2);

        uint32_t Ah = sbase + (s % 3) * STGSZ;
        uint32_t Al = Ah + REGSZ, Bh = Ah + 2 * REGSZ, Bl = Ah + 3 * REGSZ;

#pragma unroll
        for (int kk = 0; kk < 2; kk++) {
            uint32_t ah[4][4], al[4][4], bh[4][2], bl[4][2];
            int ckc = kk * 2 + lk;
#pragma unroll
            for (int mi = 0; mi < 4; mi++) {
                int row = wm + mi * 16 + lrow;
                ldsm4(ah[mi][0], ah[mi][1], ah[mi][2], ah[mi][3], swaddr(Ah, row, ckc));
                ldsm4(al[mi][0], al[mi][1], al[mi][2], al[mi][3], swaddr(Al, row, ckc));
            }
#pragma unroll
            for (int p2 = 0; p2 < 2; p2++) {
                int row = wn + p2 * 16 + lrow;
                uint32_t r0, r1, r2, r3;
                ldsm4(r0, r1, r2, r3, swaddr(Bh, row, ckc));
                bh[2 * p2][0] = r0; bh[2 * p2][1] = r2;
                bh[2 * p2 + 1][0] = r1; bh[2 * p2 + 1][1] = r3;
                ldsm4(r0, r1, r2, r3, swaddr(Bl, row, ckc));
                bl[2 * p2][0] = r0; bl[2 * p2][1] = r2;
                bl[2 * p2 + 1][0] = r1; bl[2 * p2 + 1][1] = r3;
            }
#pragma unroll
            for (int mi = 0; mi < 4; mi++)
#pragma unroll
                for (int ni = 0; ni < 4; ni++) {
                    float* c = acc[mi][ni];
                    mma16816(c[0], c[1], c[2], c[3],
                             ah[mi][0], ah[mi][1], ah[mi][2], ah[mi][3],
                             bh[ni][0], bh[ni][1]);
                    mma16816(c[0], c[1], c[2], c[3],
                             ah[mi][0], ah[mi][1], ah[mi][2], ah[mi][3],
                             bl[ni][0], bl[ni][1]);
                    mma16816(c[0], c[1], c[2], c[3],
                             al[mi][0], al[mi][1], al[mi][2], al[mi][3],
                             bh[ni][0], bh[ni][1]);
                }
        }
    }
    __syncthreads();

    // epilogue
#pragma unroll
    for (int mi = 0; mi < 4; mi++) {
#pragma unroll
        for (int ni = 0; ni < 4; ni++) {
            int col = n0 + wn + ni * 8 + 2 * q;
            float bb0 = bias[col], bb1 = bias[col + 1];
            int row0 = m0 + wm + mi * 16 + grp;
            int row1 = row0 + 8;
            float* c = acc[mi][ni];
            if (MODE == 0) {
                if (row0 < 20000) {
                    float v0 = fmaxf(c[0] + bb0, 0.f), v1 = fmaxf(c[1] + bb1, 0.f);
                    __nv_bfloat16 h0 = __float2bfloat16_rn(v0), h1 = __float2bfloat16_rn(v1);
                    __nv_bfloat162 hh; hh.x = h0; hh.y = h1;
                    __nv_bfloat162 ll;
                    ll.x = __float2bfloat16_rn(v0 - __bfloat162float(h0));
                    ll.y = __float2bfloat16_rn(v1 - __bfloat162float(h1));
                    *(__nv_bfloat162*)&g_zch[row0 * 512 + 256 + col] = hh;
                    *(__nv_bfloat162*)&g_zcl[row0 * 512 + 256 + col] = ll;
                }
                if (row1 < 20000) {
                    float v0 = fmaxf(c[2] + bb0, 0.f), v1 = fmaxf(c[3] + bb1, 0.f);
                    __nv_bfloat16 h0 = __float2bfloat16_rn(v0), h1 = __float2bfloat16_rn(v1);
                    __nv_bfloat162 hh; hh.x = h0; hh.y = h1;
                    __nv_bfloat162 ll;
                    ll.x = __float2bfloat16_rn(v0 - __bfloat162float(h0));
                    ll.y = __float2bfloat16_rn(v1 - __bfloat162float(h1));
                    *(__nv_bfloat162*)&g_zch[row1 * 512 + 256 + col] = hh;
                    *(__nv_bfloat162*)&g_zcl[row1 * 512 + 256 + col] = ll;
                }
            } else {
                if (row0 < 20000)
                    *(float2*)&g_c3[row0 * 256 + col] = make_float2(c[0] + bb0, c[1] + bb1);
                if (row1 < 20000)
                    *(float2*)&g_c3[row1 * 256 + col] = make_float2(c[2] + bb0, c[3] + bb1);
            }
        }
    }
}

// ---------------------------------------------------------------------------
// u[n][b][o] = pcb[n][o] + sum_i caps[b][n][i] * pcw[n][o][i]
// ---------------------------------------------------------------------------
__global__ void k_caps_u(const float* __restrict__ pcw,
                         const float* __restrict__ pcb) {
    int t = threadIdx.x;
    int b = t >> 3, o = t & 7;
    int n0 = blockIdx.x * 8;
#pragma unroll
    for (int ln = 0; ln < 8; ln++) {
        int n = n0 + ln;
        int g = n / 625, hw = n - g * 625;
        const float* pw = pcw + n * 64 + o * 8;
        const float* cp = &g_c3[(b * 625 + hw) * 256 + g * 8];
        float u = __ldg(&pcb[n * 8 + o]);
#pragma unroll
        for (int i = 0; i < 8; i++) u += __ldg(&cp[i]) * __ldg(&pw[i]);
        g_u[n * 256 + t] = u;
    }
}

// ---------------------------------------------------------------------------
// Fused routing pass. Recomputes u_hat from u and W on the fly.
// Block: 256 thr = 8 warps; warp w handles batches 4w..4w+3 for 32 n.
// Lane = eh*16+o ; ep loop covers e = 2*ep+eh.
// PASS 0: S0 += sum_n u_hat                (uniform c folded later via scale)
// PASS 1: logits = u_hat.v0 ; c=softmax ; S1 += c*u_hat
// PASS 2: logits = u_hat.v0 + u_hat.v1 ; c=softmax ; S2 += c*u_hat
// ---------------------------------------------------------------------------
template<int PASS>
__global__ void __launch_bounds__(256) k_pass(const float* __restrict__ W) {
    __shared__ float sW[8 * 128];    // [i][e*16+o]
    int tid = threadIdx.x, wid = tid >> 5, lane = tid & 31;
    int b0 = wid * 4;
    int n0 = blockIdx.x * 32;

    float vv0[4][4], vv1[4][4];
    if (PASS >= 1) {
#pragma unroll
        for (int bb = 0; bb < 4; bb++)
#pragma unroll
            for (int ep = 0; ep < 4; ep++) {
                vv0[bb][ep] = g_v0[(b0 + bb) * 128 + ep * 32 + lane];
                if (PASS == 2)
                    vv1[bb][ep] = g_v1[(b0 + bb) * 128 + ep * 32 + lane];
            }
    }

    float accS[4][4];
#pragma unroll
    for (int bb = 0; bb < 4; bb++)
#pragma unroll
        for (int ep = 0; ep < 4; ep++) accS[bb][ep] = 0.f;

    for (int nn = 0; nn < 32; nn++) {
        int n = n0 + nn;
        __syncthreads();
        {
            float4 wv = *(const float4*)&W[(size_t)n * 1024 + tid * 4];
            int eo = tid >> 1, i0 = (tid & 1) * 4;
            sW[(i0 + 0) * 128 + eo] = wv.x;
            sW[(i0 + 1) * 128 + eo] = wv.y;
            sW[(i0 + 2) * 128 + eo] = wv.z;
            sW[(i0 + 3) * 128 + eo] = wv.w;
        }
        __syncthreads();

        float ureg = g_u[n * 256 + b0 * 8 + lane];   // (b0+lane>>3, i=lane&7)

        float uh[4][4];
#pragma unroll
        for (int bb = 0; bb < 4; bb++)
#pragma unroll
            for (int ep = 0; ep < 4; ep++) uh[bb][ep] = 0.f;

#pragma unroll
        for (int i = 0; i < 8; i++) {
            float ub[4];
#pragma unroll
            for (int bb = 0; bb < 4; bb++)
                ub[bb] = __shfl_sync(0xffffffffu, ureg, bb * 8 + i);
#pragma unroll
            for (int ep = 0; ep < 4; ep++) {
                float w = sW[i * 128 + ep * 32 + lane];
#pragma unroll
                for (int bb = 0; bb < 4; bb++) uh[bb][ep] += ub[bb] * w;
            }
        }

        if (PASS == 0) {
#pragma unroll
            for (int bb = 0; bb < 4; bb++)
#pragma unroll
                for (int ep = 0; ep < 4; ep++) accS[bb][ep] += uh[bb][ep];
        } else {
#pragma unroll
            for (int bb = 0; bb < 4; bb++) {
                float a[4], m4 = -1e30f;
#pragma unroll
                for (int ep = 0; ep < 4; ep++) {
                    float p = uh[bb][ep] * vv0[bb][ep];
                    if (PASS == 2) p += uh[bb][ep] * vv1[bb][ep];
#pragma unroll
                    for (int off = 8; off; off >>= 1)
                        p += __shfl_xor_sync(0xffffffffu, p, off);
                    a[ep] = p;
                    m4 = fmaxf(m4, p);
                }
                float amax = fmaxf(m4, __shfl_xor_sync(0xffffffffu, m4, 16));
                float ex[4], s4 = 0.f;
#pragma unroll
                for (int ep = 0; ep < 4; ep++) { ex[ep] = __expf(a[ep] - amax); s4 += ex[ep]; }
                float Z = s4 + __shfl_xor_sync(0xffffffffu, s4, 16);
                float rZ = 1.f / Z;
#pragma unroll
                for (int ep = 0; ep < 4; ep++)
                    accS[bb][ep] += ex[ep] * rZ * uh[bb][ep];
            }
        }
    }

    float* Sout = (PASS == 0) ? g_S0 : (PASS == 1) ? g_S1 : g_S2;
#pragma unroll
    for (int bb = 0; bb < 4; bb++)
#pragma unroll
        for (int ep = 0; ep < 4; ep++)
            atomicAdd(&Sout[(b0 + bb) * 128 + ep * 32 + lane], accS[bb][ep]);
}

// squash S -> v
__global__ void k_squash(int which, float scale) {
    int b = blockIdx.x, t = threadIdx.x;
    const float* S = (which == 0) ? g_S0 : (which == 1) ? g_S1 : g_S2;
    float* V = (which == 0) ? g_v0 : (which == 1) ? g_v1 : g_v2;
    float s = S[b * 128 + t] * scale;
    float n2 = s * s;
#pragma unroll
    for (int off = 8; off; off >>= 1)
        n2 += __shfl_xor_sync(0xffffffffu, n2, off);
    float nn = sqrtf(n2);
    V[b * 128 + t] = (n2 / (1.f + n2)) * s / (nn + 1e-8f);
}

__global__ void k_final(float* __restrict__ out) {
    int b = blockIdx.x, t = threadIdx.x;
    float v = g_v2[b * 128 + t];
    float s = v * v;
#pragma unroll
    for (int off = 8; off; off >>= 1)
        s += __shfl_xor_sync(0xffffffffu, s, off);
    if ((t & 15) == 0) out[b * 8 + (t >> 4)] = sqrtf(s);
}

// ===========================================================================
extern "C" void kernel_launch(void* const* d_in, const int* in_sizes, int n_in,
                              void* d_out, int out_size) {
    const float* x   = (const float*)d_in[0];
    const float* w1  = (const float*)d_in[1];
    const float* b1  = (const float*)d_in[2];
    const float* w2  = (const float*)d_in[3];
    const float* b2  = (const float*)d_in[4];
    const float* w3  = (const float*)d_in[5];
    const float* b3  = (const float*)d_in[6];
    const float* pcw = (const float*)d_in[7];
    const float* pcb = (const float*)d_in[8];
    const float* W   = (const float*)d_in[9];
    float* out = (float*)d_out;

    cudaFuncSetAttribute(k_gemm2<0>, cudaFuncAttributeMaxDynamicSharedMemorySize, SMEM_GEMM);
    cudaFuncSetAttribute(k_gemm2<1>, cudaFuncAttributeMaxDynamicSharedMemorySize, SMEM_GEMM);

    k_zero_all<<<14400, 256>>>();
    k_conv1<<<20000, 256>>>(x, w1, b1);
    k_prep_w2s<<<256, 256>>>(w2);
    k_gemm2<0><<<dim3(157, 2), 256, SMEM_GEMM>>>(b2);   // conv2 (profiled slot)
    k_prep_w3s<<<512, 256>>>(w3);
    k_gemm2<1><<<dim3(157, 2), 256, SMEM_GEMM>>>(b3);   // conv3
    k_caps_u<<<2500, 256>>>(pcw, pcb);
    k_pass<0><<<625, 256>>>(W);
    k_squash<<<32, 128>>>(0, 0.125f);
    k_pass<1><<<625, 256>>>(W);
    k_squash<<<32, 128>>>(1, 1.f);
    k_pass<2><<<625, 256>>>(W);
    k_squash<<<32, 128>>>(2, 1.f);
    k_final<<<32, 128>>>(out);
}

// round 8
// speedup vs baseline: 2.7466x; 1.3806x over previous
#include <cuda_runtime.h>
#include <cuda_fp16.h>
#include <math.h>
#include <cstdint>

// ===========================================================================
//   conv1 -> conv2 (implicit GEMM M=20000,N=256,K=9216)
//   conv3 (K=512) -> u -> fused routing (on-the-fly u_hat)
//   GEMMs: mma.sync fp16, A single + B hi/lo 2-term split, fp32 accum.
//   Grid (148,2), M-tile 160 overlapping starts -> perfectly balanced waves.
// ===========================================================================

__device__ __align__(16) __half g_xpf[32 * 30 * 30 * 256];   // padded conv1 (fp16)
__device__ __align__(16) __half g_zc[20000 * 512];           // [conv1|conv2] fp16
__device__ __align__(16) __half g_w2fh[256 * 9216];
__device__ __align__(16) __half g_w2fl[256 * 9216];
__device__ __align__(16) __half g_w3fh[256 * 512];
__device__ __align__(16) __half g_w3fl[256 * 512];
__device__ float g_c3[20000 * 256];
__device__ float g_u[20000 * 256];       // u[n][b*8+o]
__device__ float g_S0[32 * 128];
__device__ float g_S1[32 * 128];
__device__ float g_S2[32 * 128];
__device__ float g_v0[32 * 128];
__device__ float g_v1[32 * 128];
__device__ float g_v2[32 * 128];

// ---------------------------------------------------------------------------
__global__ void k_zero_all() {
    int i = blockIdx.x * 256 + threadIdx.x;
    if (i < 3686400) ((uint32_t*)g_xpf)[i] = 0u;    // 7372800 halves
    if (i < 32 * 128) { g_S0[i] = 0.f; g_S1[i] = 0.f; g_S2[i] = 0.f; }
}

__global__ void k_conv1(const float* __restrict__ x,
                        const float* __restrict__ w1,
                        const float* __restrict__ b1) {
    __shared__ float xs[36];
    int blk = blockIdx.x;
    int b = blk / 625, p = blk % 625, oh = p / 25, ow = p % 25;
    int t = threadIdx.x;
    if (t < 36) {
        int kh = t / 6, kw = t % 6;
        xs[t] = x[b * 2916 + (2 * oh + kh) * 54 + (2 * ow + kw)];
    }
    __syncthreads();
    float acc = b1[t];
#pragma unroll
    for (int j = 0; j < 36; j++) acc += xs[j] * __ldg(&w1[t * 36 + j]);
    acc = fmaxf(acc, 0.f);
    __half h = __float2half_rn(acc);
    g_xpf[((b * 30 + oh + 2) * 30 + (ow + 2)) * 256 + t] = h;
    g_zc[(b * 625 + oh * 25 + ow) * 512 + t] = h;
}

// conv2 weights (oc,ic,kh,kw) -> fp16 hi/lo [oc][khw*256+ic]
__global__ void k_prep_w2s(const float* __restrict__ w2) {
    __shared__ float s[256 * 37];
    int oc = blockIdx.x;
    int t = threadIdx.x;
    for (int j = 0; j < 36; j++) {
        int idx = t + 256 * j;
        int ic = idx / 36, khw = idx % 36;
        s[ic * 37 + khw] = w2[oc * 9216 + idx];
    }
    __syncthreads();
    for (int j = 0; j < 36; j++) {
        int o = t + 256 * j;
        int khw = o >> 8, ic = o & 255;
        float v = s[ic * 37 + khw];
        __half h = __float2half_rn(v);
        g_w2fh[oc * 9216 + o] = h;
        g_w2fl[oc * 9216 + o] = __float2half_rn(v - __half2float(h));
    }
}
__global__ void k_prep_w3s(const float* __restrict__ w3) {
    int i = blockIdx.x * 256 + threadIdx.x;
    if (i < 131072) {
        float v = w3[i];
        __half h = __float2half_rn(v);
        g_w3fh[i] = h;
        g_w3fl[i] = __float2half_rn(v - __half2float(h));
    }
}

// ---------------------------------------------------------------------------
// GEMM helpers
// ---------------------------------------------------------------------------
__device__ __forceinline__ uint32_t smem_u32(const void* p) {
    uint32_t a;
    asm("{ .reg .u64 t; cvta.to.shared.u64 t, %1; cvt.u32.u64 %0, t; }" : "=r"(a) : "l"(p));
    return a;
}
__device__ __forceinline__ void cpa16(uint32_t d, const void* g) {
    asm volatile("cp.async.cg.shared.global [%0], [%1], 16;" :: "r"(d), "l"(g) : "memory");
}
#define CP_COMMIT() asm volatile("cp.async.commit_group;" ::: "memory")
#define CP_WAIT(n)  asm volatile("cp.async.wait_group %0;" :: "n"(n) : "memory")

__device__ __forceinline__ void ldsm4(uint32_t& r0, uint32_t& r1, uint32_t& r2, uint32_t& r3,
                                      uint32_t a) {
    asm volatile("ldmatrix.sync.aligned.m8n8.x4.shared.b16 {%0,%1,%2,%3}, [%4];"
                 : "=r"(r0), "=r"(r1), "=r"(r2), "=r"(r3) : "r"(a));
}
__device__ __forceinline__ void mma16816(float& c0, float& c1, float& c2, float& c3,
                                         uint32_t a0, uint32_t a1, uint32_t a2, uint32_t a3,
                                         uint32_t b0, uint32_t b1) {
    asm volatile("mma.sync.aligned.m16n8k16.row.col.f32.f16.f16.f32 "
                 "{%0,%1,%2,%3}, {%4,%5,%6,%7}, {%8,%9}, {%0,%1,%2,%3};"
                 : "+f"(c0), "+f"(c1), "+f"(c2), "+f"(c3)
                 : "r"(a0), "r"(a1), "r"(a2), "r"(a3), "r"(b0), "r"(b1));
}

__device__ __forceinline__ uint32_t swaddr(uint32_t region, int row, int chunk) {
    return region + (uint32_t)row * 64u + (uint32_t)((chunk ^ ((row >> 1) & 3)) << 4);
}

// stage: A 160x32 fp16 (10240B) | Bh 128x32 (8192B) | Bl 128x32 (8192B)
#define OFF_A  0
#define OFF_BH 10240
#define OFF_BL 18432
#define STGSZ  26624
#define SMEM_GEMM (3 * STGSZ)
#define NCHUNK 1664   // (160+128+128)*4

template<int MODE>
__global__ void __launch_bounds__(256, 2) k_gemm2(const float* __restrict__ bias) {
    constexpr int K = (MODE == 0) ? 9216 : 512;
    constexpr int S = K / 32;
    extern __shared__ char sm[];
    __shared__ int s_rowbase[160];
    const uint32_t sbase = smem_u32(sm);
    const int tid = threadIdx.x;
    const int m0 = (int)(((long long)blockIdx.x * 19840) / 147);   // 0..19840
    const int n0 = blockIdx.y * 128;

    if (MODE == 0 && tid < 160) {
        int m = m0 + tid;
        int b = m / 625, p = m % 625, oh = p / 25, ow = p % 25;
        s_rowbase[tid] = ((b * 30 + oh) * 30 + ow) * 256;
    }
    __syncthreads();

    const __half* WH = (MODE == 0) ? g_w2fh : g_w3fh;
    const __half* WL = (MODE == 0) ? g_w2fl : g_w3fl;

    auto issue = [&](int s) {
        int k0 = s * 32;
        uint32_t dbase = sbase + (s % 3) * STGSZ;
        int aoff = 0;
        if (MODE == 0) {
            int khw = k0 >> 8;
            int kh = khw / 6, kw = khw - kh * 6;
            aoff = (kh * 30 + kw) * 256 + (k0 & 255);
        }
#pragma unroll
        for (int j = 0; j < 7; j++) {
            int c = tid + j * 256;
            if (c < 640) {                       // A region
                int row = c >> 2, kc = c & 3;
                const __half* src;
                if (MODE == 0) src = g_xpf + s_rowbase[row] + aoff + kc * 8;
                else           src = g_zc + (size_t)(m0 + row) * 512 + k0 + kc * 8;
                cpa16(swaddr(dbase + OFF_A, row, kc), src);
            } else if (c < 1152) {               // Bh
                int c2 = c - 640;
                int row = c2 >> 2, kc = c2 & 3;
                cpa16(swaddr(dbase + OFF_BH, row, kc),
                      WH + (size_t)(n0 + row) * K + k0 + kc * 8);
            } else if (c < NCHUNK) {             // Bl
                int c2 = c - 1152;
                int row = c2 >> 2, kc = c2 & 3;
                cpa16(swaddr(dbase + OFF_BL, row, kc),
                      WL + (size_t)(n0 + row) * K + k0 + kc * 8);
            }
        }
        CP_COMMIT();
    };

    const int lane = tid & 31, wid = tid >> 5;
    const int wm = (wid & 1) * 80, wn = (wid >> 1) * 32;
    const int grp = lane >> 2, q = lane & 3;
    const int lrow = lane & 15, lk = lane >> 4;

    float acc[5][4][4];
#pragma unroll
    for (int i = 0; i < 5; i++)
#pragma unroll
        for (int j = 0; j < 4; j++)
#pragma unroll
            for (int c = 0; c < 4; c++) acc[i][j][c] = 0.f;

    issue(0);
    issue(1);

    for (int s = 0; s < S; s++) {
        if (s < S - 1) CP_WAIT(1); else CP_WAIT(0);
        __syncthreads();
        if (s + 2 < S) issue(s + 2);

        uint32_t Ar = sbase + (s % 3) * STGSZ + OFF_A;
        uint32_t Bh = Ar - OFF_A + OFF_BH;
        uint32_t Bl = Ar - OFF_A + OFF_BL;

#pragma unroll
        for (int kk = 0; kk < 2; kk++) {
            int ckc = kk * 2 + lk;
            uint32_t bh[4][2], bl[4][2];
#pragma unroll
            for (int p2 = 0; p2 < 2; p2++) {
                int row = wn + p2 * 16 + lrow;
                uint32_t r0, r1, r2, r3;
                ldsm4(r0, r1, r2, r3, swaddr(Bh, row, ckc));
                bh[2 * p2][0] = r0; bh[2 * p2][1] = r2;
                bh[2 * p2 + 1][0] = r1; bh[2 * p2 + 1][1] = r3;
                ldsm4(r0, r1, r2, r3, swaddr(Bl, row, ckc));
                bl[2 * p2][0] = r0; bl[2 * p2][1] = r2;
                bl[2 * p2 + 1][0] = r1; bl[2 * p2 + 1][1] = r3;
            }
#pragma unroll
            for (int mi = 0; mi < 5; mi++) {
                uint32_t a0, a1, a2, a3;
                ldsm4(a0, a1, a2, a3, swaddr(Ar, wm + mi * 16 + lrow, ckc));
#pragma unroll
                for (int ni = 0; ni < 4; ni++) {
                    float* c = acc[mi][ni];
                    mma16816(c[0], c[1], c[2], c[3], a0, a1, a2, a3,
                             bh[ni][0], bh[ni][1]);
                    mma16816(c[0], c[1], c[2], c[3], a0, a1, a2, a3,
                             bl[ni][0], bl[ni][1]);
                }
            }
        }
    }
    __syncthreads();

    // epilogue (all rows in [0,20000): no bounds checks; overlaps write same data)
#pragma unroll
    for (int mi = 0; mi < 5; mi++) {
#pragma unroll
        for (int ni = 0; ni < 4; ni++) {
            int col = n0 + wn + ni * 8 + 2 * q;
            float bb0 = bias[col], bb1 = bias[col + 1];
            int row0 = m0 + wm + mi * 16 + grp;
            int row1 = row0 + 8;
            float* c = acc[mi][ni];
            if (MODE == 0) {
                float v0 = fmaxf(c[0] + bb0, 0.f), v1 = fmaxf(c[1] + bb1, 0.f);
                __half2 h01; h01.x = __float2half_rn(v0); h01.y = __float2half_rn(v1);
                *(__half2*)&g_zc[(size_t)row0 * 512 + 256 + col] = h01;
                float v2 = fmaxf(c[2] + bb0, 0.f), v3 = fmaxf(c[3] + bb1, 0.f);
                __half2 h23; h23.x = __float2half_rn(v2); h23.y = __float2half_rn(v3);
                *(__half2*)&g_zc[(size_t)row1 * 512 + 256 + col] = h23;
            } else {
                *(float2*)&g_c3[(size_t)row0 * 256 + col] = make_float2(c[0] + bb0, c[1] + bb1);
                *(float2*)&g_c3[(size_t)row1 * 256 + col] = make_float2(c[2] + bb0, c[3] + bb1);
            }
        }
    }
}

// ---------------------------------------------------------------------------
// u[n][b][o] = pcb[n][o] + sum_i caps[b][n][i] * pcw[n][o][i]
// ---------------------------------------------------------------------------
__global__ void k_caps_u(const float* __restrict__ pcw,
                         const float* __restrict__ pcb) {
    int t = threadIdx.x;
    int b = t >> 3, o = t & 7;
    int n0 = blockIdx.x * 8;
#pragma unroll
    for (int ln = 0; ln < 8; ln++) {
        int n = n0 + ln;
        int g = n / 625, hw = n - g * 625;
        const float* pw = pcw + n * 64 + o * 8;
        const float* cp = &g_c3[(b * 625 + hw) * 256 + g * 8];
        float u = __ldg(&pcb[n * 8 + o]);
#pragma unroll
        for (int i = 0; i < 8; i++) u += __ldg(&cp[i]) * __ldg(&pw[i]);
        g_u[n * 256 + t] = u;
    }
}

// ---------------------------------------------------------------------------
// Fused routing pass, u_hat recomputed on the fly (see round-7 notes).
// ---------------------------------------------------------------------------
template<int PASS>
__global__ void __launch_bounds__(256) k_pass(const float* __restrict__ W) {
    __shared__ float sW[8 * 128];
    int tid = threadIdx.x, wid = tid >> 5, lane = tid & 31;
    int b0 = wid * 4;
    int n0 = blockIdx.x * 32;

    float vv0[4][4], vv1[4][4];
    if (PASS >= 1) {
#pragma unroll
        for (int bb = 0; bb < 4; bb++)
#pragma unroll
            for (int ep = 0; ep < 4; ep++) {
                vv0[bb][ep] = g_v0[(b0 + bb) * 128 + ep * 32 + lane];
                if (PASS == 2)
                    vv1[bb][ep] = g_v1[(b0 + bb) * 128 + ep * 32 + lane];
            }
    }

    float accS[4][4];
#pragma unroll
    for (int bb = 0; bb < 4; bb++)
#pragma unroll
        for (int ep = 0; ep < 4; ep++) accS[bb][ep] = 0.f;

    for (int nn = 0; nn < 32; nn++) {
        int n = n0 + nn;
        __syncthreads();
        {
            float4 wv = *(const float4*)&W[(size_t)n * 1024 + tid * 4];
            int eo = tid >> 1, i0 = (tid & 1) * 4;
            sW[(i0 + 0) * 128 + eo] = wv.x;
            sW[(i0 + 1) * 128 + eo] = wv.y;
            sW[(i0 + 2) * 128 + eo] = wv.z;
            sW[(i0 + 3) * 128 + eo] = wv.w;
        }
        __syncthreads();

        float ureg = g_u[n * 256 + b0 * 8 + lane];

        float uh[4][4];
#pragma unroll
        for (int bb = 0; bb < 4; bb++)
#pragma unroll
            for (int ep = 0; ep < 4; ep++) uh[bb][ep] = 0.f;

#pragma unroll
        for (int i = 0; i < 8; i++) {
            float ub[4];
#pragma unroll
            for (int bb = 0; bb < 4; bb++)
                ub[bb] = __shfl_sync(0xffffffffu, ureg, bb * 8 + i);
#pragma unroll
            for (int ep = 0; ep < 4; ep++) {
                float w = sW[i * 128 + ep * 32 + lane];
#pragma unroll
                for (int bb = 0; bb < 4; bb++) uh[bb][ep] += ub[bb] * w;
            }
        }

        if (PASS == 0) {
#pragma unroll
            for (int bb = 0; bb < 4; bb++)
#pragma unroll
                for (int ep = 0; ep < 4; ep++) accS[bb][ep] += uh[bb][ep];
        } else {
#pragma unroll
            for (int bb = 0; bb < 4; bb++) {
                float a[4], m4 = -1e30f;
#pragma unroll
                for (int ep = 0; ep < 4; ep++) {
                    float p = uh[bb][ep] * vv0[bb][ep];
                    if (PASS == 2) p += uh[bb][ep] * vv1[bb][ep];
#pragma unroll
                    for (int off = 8; off; off >>= 1)
                        p += __shfl_xor_sync(0xffffffffu, p, off);
                    a[ep] = p;
                    m4 = fmaxf(m4, p);
                }
                float amax = fmaxf(m4, __shfl_xor_sync(0xffffffffu, m4, 16));
                float ex[4], s4 = 0.f;
#pragma unroll
                for (int ep = 0; ep < 4; ep++) { ex[ep] = __expf(a[ep] - amax); s4 += ex[ep]; }
                float Z = s4 + __shfl_xor_sync(0xffffffffu, s4, 16);
                float rZ = 1.f / Z;
#pragma unroll
                for (int ep = 0; ep < 4; ep++)
                    accS[bb][ep] += ex[ep] * rZ * uh[bb][ep];
            }
        }
    }

    float* Sout = (PASS == 0) ? g_S0 : (PASS == 1) ? g_S1 : g_S2;
#pragma unroll
    for (int bb = 0; bb < 4; bb++)
#pragma unroll
        for (int ep = 0; ep < 4; ep++)
            atomicAdd(&Sout[(b0 + bb) * 128 + ep * 32 + lane], accS[bb][ep]);
}

__global__ void k_squash(int which, float scale) {
    int b = blockIdx.x, t = threadIdx.x;
    const float* S = (which == 0) ? g_S0 : (which == 1) ? g_S1 : g_S2;
    float* V = (which == 0) ? g_v0 : (which == 1) ? g_v1 : g_v2;
    float s = S[b * 128 + t] * scale;
    float n2 = s * s;
#pragma unroll
    for (int off = 8; off; off >>= 1)
        n2 += __shfl_xor_sync(0xffffffffu, n2, off);
    float nn = sqrtf(n2);
    V[b * 128 + t] = (n2 / (1.f + n2)) * s / (nn + 1e-8f);
}

__global__ void k_final(float* __restrict__ out) {
    int b = blockIdx.x, t = threadIdx.x;
    float v = g_v2[b * 128 + t];
    float s = v * v;
#pragma unroll
    for (int off = 8; off; off >>= 1)
        s += __shfl_xor_sync(0xffffffffu, s, off);
    if ((t & 15) == 0) out[b * 8 + (t >> 4)] = sqrtf(s);
}

// ===========================================================================
extern "C" void kernel_launch(void* const* d_in, const int* in_sizes, int n_in,
                              void* d_out, int out_size) {
    const float* x   = (const float*)d_in[0];
    const float* w1  = (const float*)d_in[1];
    const float* b1  = (const float*)d_in[2];
    const float* w2  = (const float*)d_in[3];
    const float* b2  = (const float*)d_in[4];
    const float* w3  = (const float*)d_in[5];
    const float* b3  = (const float*)d_in[6];
    const float* pcw = (const float*)d_in[7];
    const float* pcb = (const float*)d_in[8];
    const float* W   = (const float*)d_in[9];
    float* out = (float*)d_out;

    cudaFuncSetAttribute(k_gemm2<0>, cudaFuncAttributeMaxDynamicSharedMemorySize, SMEM_GEMM);
    cudaFuncSetAttribute(k_gemm2<1>, cudaFuncAttributeMaxDynamicSharedMemorySize, SMEM_GEMM);

    k_zero_all<<<14400, 256>>>();
    k_conv1<<<20000, 256>>>(x, w1, b1);
    k_prep_w2s<<<256, 256>>>(w2);
    k_gemm2<0><<<dim3(148, 2), 256, SMEM_GEMM>>>(b2);   // conv2 (profiled slot)
    k_prep_w3s<<<512, 256>>>(w3);
    k_gemm2<1><<<dim3(148, 2), 256, SMEM_GEMM>>>(b3);   // conv3
    k_caps_u<<<2500, 256>>>(pcw, pcb);
    k_pass<0><<<625, 256>>>(W);
    k_squash<<<32, 128>>>(0, 0.125f);
    k_pass<1><<<625, 256>>>(W);
    k_squash<<<32, 128>>>(1, 1.f);
    k_pass<2><<<625, 256>>>(W);
    k_squash<<<32, 128>>>(2, 1.f);
    k_final<<<32, 128>>>(out);
}

// round 9
// speedup vs baseline: 4.1280x; 1.5029x over previous
#include <cuda_runtime.h>
#include <cuda_fp16.h>
#include <math.h>
#include <cstdint>

// ===========================================================================
//   conv1 -> conv2 (implicit GEMM M=20000,N=256,K=9216)
//   conv3 (K=512) -> u -> fused routing (on-the-fly u_hat)
//   GEMMs: single-term fp16 mma.sync, fp32 accum (rel_err ~3e-5, gate 1e-3).
//   Grid (148,2), M-tile 160 overlapping starts -> perfectly balanced waves.
// ===========================================================================

__device__ __align__(16) __half g_xpf[32 * 30 * 30 * 256];   // padded conv1 (fp16)
__device__ __align__(16) __half g_zc[20000 * 512];           // [conv1|conv2] fp16
__device__ __align__(16) __half g_w2f[256 * 9216];
__device__ __align__(16) __half g_w3f[256 * 512];
__device__ float g_c3[20000 * 256];
__device__ float g_u[20000 * 256];       // u[n][b*8+o]
__device__ float g_S0[32 * 128];
__device__ float g_S1[32 * 128];
__device__ float g_S2[32 * 128];
__device__ float g_v0[32 * 128];
__device__ float g_v1[32 * 128];
__device__ float g_v2[32 * 128];

// ---------------------------------------------------------------------------
__global__ void k_zero_all() {
    int i = blockIdx.x * 256 + threadIdx.x;
    if (i < 3686400) ((uint32_t*)g_xpf)[i] = 0u;    // 7372800 halves
    if (i < 32 * 128) { g_S0[i] = 0.f; g_S1[i] = 0.f; g_S2[i] = 0.f; }
}

// conv1: block = (batch, 5 output rows). w1 taps in registers, x tile in smem.
__global__ void __launch_bounds__(256) k_conv1(const float* __restrict__ x,
                                               const float* __restrict__ w1,
                                               const float* __restrict__ b1) {
    __shared__ float xs[14 * 54];
    int b = blockIdx.x;
    int r0 = blockIdx.y * 5;            // output rows r0..r0+4
    int t = threadIdx.x;                // oc

    for (int idx = t; idx < 14 * 54; idx += 256) {
        int row = idx / 54, col = idx % 54;
        xs[idx] = x[b * 2916 + (2 * r0 + row) * 54 + col];
    }
    float wr[36];
#pragma unroll
    for (int j = 0; j < 36; j++) wr[j] = __ldg(&w1[t * 36 + j]);
    float bias = __ldg(&b1[t]);
    __syncthreads();

    for (int pr = 0; pr < 5; pr++) {
        int oh = r0 + pr;
#pragma unroll 5
        for (int ow = 0; ow < 25; ow++) {
            float acc = bias;
#pragma unroll
            for (int kh = 0; kh < 6; kh++)
#pragma unroll
                for (int kw = 0; kw < 6; kw++)
                    acc += xs[(2 * pr + kh) * 54 + 2 * ow + kw] * wr[kh * 6 + kw];
            acc = fmaxf(acc, 0.f);
            __half h = __float2half_rn(acc);
            g_xpf[((b * 30 + oh + 2) * 30 + (ow + 2)) * 256 + t] = h;
            g_zc[(b * 625 + oh * 25 + ow) * 512 + t] = h;
        }
    }
}

// conv2 weights (oc,ic,kh,kw) -> fp16 [oc][khw*256+ic]
__global__ void k_prep_w2s(const float* __restrict__ w2) {
    __shared__ float s[256 * 37];
    int oc = blockIdx.x;
    int t = threadIdx.x;
    for (int j = 0; j < 36; j++) {
        int idx = t + 256 * j;
        int ic = idx / 36, khw = idx % 36;
        s[ic * 37 + khw] = w2[oc * 9216 + idx];
    }
    __syncthreads();
    for (int j = 0; j < 36; j++) {
        int o = t + 256 * j;
        int khw = o >> 8, ic = o & 255;
        g_w2f[oc * 9216 + o] = __float2half_rn(s[ic * 37 + khw]);
    }
}
__global__ void k_prep_w3s(const float* __restrict__ w3) {
    int i = blockIdx.x * 256 + threadIdx.x;
    if (i < 131072) g_w3f[i] = __float2half_rn(w3[i]);
}

// ---------------------------------------------------------------------------
// GEMM helpers
// ---------------------------------------------------------------------------
__device__ __forceinline__ uint32_t smem_u32(const void* p) {
    uint32_t a;
    asm("{ .reg .u64 t; cvta.to.shared.u64 t, %1; cvt.u32.u64 %0, t; }" : "=r"(a) : "l"(p));
    return a;
}
__device__ __forceinline__ void cpa16(uint32_t d, const void* g) {
    asm volatile("cp.async.cg.shared.global [%0], [%1], 16;" :: "r"(d), "l"(g) : "memory");
}
#define CP_COMMIT() asm volatile("cp.async.commit_group;" ::: "memory")
#define CP_WAIT(n)  asm volatile("cp.async.wait_group %0;" :: "n"(n) : "memory")

__device__ __forceinline__ void ldsm4(uint32_t& r0, uint32_t& r1, uint32_t& r2, uint32_t& r3,
                                      uint32_t a) {
    asm volatile("ldmatrix.sync.aligned.m8n8.x4.shared.b16 {%0,%1,%2,%3}, [%4];"
                 : "=r"(r0), "=r"(r1), "=r"(r2), "=r"(r3) : "r"(a));
}
__device__ __forceinline__ void mma16816(float& c0, float& c1, float& c2, float& c3,
                                         uint32_t a0, uint32_t a1, uint32_t a2, uint32_t a3,
                                         uint32_t b0, uint32_t b1) {
    asm volatile("mma.sync.aligned.m16n8k16.row.col.f32.f16.f16.f32 "
                 "{%0,%1,%2,%3}, {%4,%5,%6,%7}, {%8,%9}, {%0,%1,%2,%3};"
                 : "+f"(c0), "+f"(c1), "+f"(c2), "+f"(c3)
                 : "r"(a0), "r"(a1), "r"(a2), "r"(a3), "r"(b0), "r"(b1));
}

__device__ __forceinline__ uint32_t swaddr(uint32_t region, int row, int chunk) {
    return region + (uint32_t)row * 64u + (uint32_t)((chunk ^ ((row >> 1) & 3)) << 4);
}

// stage: A 160x32 fp16 (10240B) | B 128x32 (8192B)
#define OFF_B  10240
#define STGSZ  18432
#define SMEM_GEMM (3 * STGSZ)
#define NCHUNK 1152   // (160+128)*4

template<int MODE>
__global__ void __launch_bounds__(256, 2) k_gemm2(const float* __restrict__ bias) {
    constexpr int K = (MODE == 0) ? 9216 : 512;
    constexpr int S = K / 32;
    extern __shared__ char sm[];
    __shared__ int s_rowbase[160];
    const uint32_t sbase = smem_u32(sm);
    const int tid = threadIdx.x;
    const int m0 = (int)(((long long)blockIdx.x * 19840) / 147);   // 0..19840
    const int n0 = blockIdx.y * 128;

    if (MODE == 0 && tid < 160) {
        int m = m0 + tid;
        int b = m / 625, p = m % 625, oh = p / 25, ow = p % 25;
        s_rowbase[tid] = ((b * 30 + oh) * 30 + ow) * 256;
    }
    __syncthreads();

    const __half* WH = (MODE == 0) ? g_w2f : g_w3f;

    auto issue = [&](int s) {
        int k0 = s * 32;
        uint32_t dbase = sbase + (s % 3) * STGSZ;
        int aoff = 0;
        if (MODE == 0) {
            int khw = k0 >> 8;
            int kh = khw / 6, kw = khw - kh * 6;
            aoff = (kh * 30 + kw) * 256 + (k0 & 255);
        }
#pragma unroll
        for (int j = 0; j < 5; j++) {
            int c = tid + j * 256;
            if (c < 640) {                       // A region
                int row = c >> 2, kc = c & 3;
                const __half* src;
                if (MODE == 0) src = g_xpf + s_rowbase[row] + aoff + kc * 8;
                else           src = g_zc + (size_t)(m0 + row) * 512 + k0 + kc * 8;
                cpa16(swaddr(dbase, row, kc), src);
            } else if (c < NCHUNK) {             // B
                int c2 = c - 640;
                int row = c2 >> 2, kc = c2 & 3;
                cpa16(swaddr(dbase + OFF_B, row, kc),
                      WH + (size_t)(n0 + row) * K + k0 + kc * 8);
            }
        }
        CP_COMMIT();
    };

    const int lane = tid & 31, wid = tid >> 5;
    const int wm = (wid & 1) * 80, wn = (wid >> 1) * 32;
    const int grp = lane >> 2, q = lane & 3;
    const int lrow = lane & 15, lk = lane >> 4;

    float acc[5][4][4];
#pragma unroll
    for (int i = 0; i < 5; i++)
#pragma unroll
        for (int j = 0; j < 4; j++)
#pragma unroll
            for (int c = 0; c < 4; c++) acc[i][j][c] = 0.f;

    issue(0);
    issue(1);

    for (int s = 0; s < S; s++) {
        if (s < S - 1) CP_WAIT(1); else CP_WAIT(0);
        __syncthreads();
        if (s + 2 < S) issue(s + 2);

        uint32_t Ar = sbase + (s % 3) * STGSZ;
        uint32_t Br = Ar + OFF_B;

#pragma unroll
        for (int kk = 0; kk < 2; kk++) {
            int ckc = kk * 2 + lk;
            uint32_t bh[4][2];
#pragma unroll
            for (int p2 = 0; p2 < 2; p2++) {
                int row = wn + p2 * 16 + lrow;
                uint32_t r0, r1, r2, r3;
                ldsm4(r0, r1, r2, r3, swaddr(Br, row, ckc));
                bh[2 * p2][0] = r0; bh[2 * p2][1] = r2;
                bh[2 * p2 + 1][0] = r1; bh[2 * p2 + 1][1] = r3;
            }
#pragma unroll
            for (int mi = 0; mi < 5; mi++) {
                uint32_t a0, a1, a2, a3;
                ldsm4(a0, a1, a2, a3, swaddr(Ar, wm + mi * 16 + lrow, ckc));
#pragma unroll
                for (int ni = 0; ni < 4; ni++) {
                    float* c = acc[mi][ni];
                    mma16816(c[0], c[1], c[2], c[3], a0, a1, a2, a3,
                             bh[ni][0], bh[ni][1]);
                }
            }
        }
    }
    __syncthreads();

    // epilogue (all rows in [0,20000): overlapping tiles write identical data)
#pragma unroll
    for (int mi = 0; mi < 5; mi++) {
#pragma unroll
        for (int ni = 0; ni < 4; ni++) {
            int col = n0 + wn + ni * 8 + 2 * q;
            float bb0 = bias[col], bb1 = bias[col + 1];
            int row0 = m0 + wm + mi * 16 + grp;
            int row1 = row0 + 8;
            float* c = acc[mi][ni];
            if (MODE == 0) {
                float v0 = fmaxf(c[0] + bb0, 0.f), v1 = fmaxf(c[1] + bb1, 0.f);
                __half2 h01; h01.x = __float2half_rn(v0); h01.y = __float2half_rn(v1);
                *(__half2*)&g_zc[(size_t)row0 * 512 + 256 + col] = h01;
                float v2 = fmaxf(c[2] + bb0, 0.f), v3 = fmaxf(c[3] + bb1, 0.f);
                __half2 h23; h23.x = __float2half_rn(v2); h23.y = __float2half_rn(v3);
                *(__half2*)&g_zc[(size_t)row1 * 512 + 256 + col] = h23;
            } else {
                *(float2*)&g_c3[(size_t)row0 * 256 + col] = make_float2(c[0] + bb0, c[1] + bb1);
                *(float2*)&g_c3[(size_t)row1 * 256 + col] = make_float2(c[2] + bb0, c[3] + bb1);
            }
        }
    }
}

// ---------------------------------------------------------------------------
// u[n][b][o] = pcb[n][o] + sum_i caps[b][n][i] * pcw[n][o][i]
// ---------------------------------------------------------------------------
__global__ void k_caps_u(const float* __restrict__ pcw,
                         const float* __restrict__ pcb) {
    int t = threadIdx.x;
    int b = t >> 3, o = t & 7;
    int n0 = blockIdx.x * 8;
#pragma unroll
    for (int ln = 0; ln < 8; ln++) {
        int n = n0 + ln;
        int g = n / 625, hw = n - g * 625;
        const float* pw = pcw + n * 64 + o * 8;
        const float* cp = &g_c3[(b * 625 + hw) * 256 + g * 8];
        float u = __ldg(&pcb[n * 8 + o]);
#pragma unroll
        for (int i = 0; i < 8; i++) u += __ldg(&cp[i]) * __ldg(&pw[i]);
        g_u[n * 256 + t] = u;
    }
}

// ---------------------------------------------------------------------------
// Fused routing pass, u_hat recomputed on the fly.
// ---------------------------------------------------------------------------
template<int PASS>
__global__ void __launch_bounds__(256) k_pass(const float* __restrict__ W) {
    __shared__ float sW[8 * 128];
    int tid = threadIdx.x, wid = tid >> 5, lane = tid & 31;
    int b0 = wid * 4;
    int n0 = blockIdx.x * 32;

    float vv0[4][4], vv1[4][4];
    if (PASS >= 1) {
#pragma unroll
        for (int bb = 0; bb < 4; bb++)
#pragma unroll
            for (int ep = 0; ep < 4; ep++) {
                vv0[bb][ep] = g_v0[(b0 + bb) * 128 + ep * 32 + lane];
                if (PASS == 2)
                    vv1[bb][ep] = g_v1[(b0 + bb) * 128 + ep * 32 + lane];
            }
    }

    float accS[4][4];
#pragma unroll
    for (int bb = 0; bb < 4; bb++)
#pragma unroll
        for (int ep = 0; ep < 4; ep++) accS[bb][ep] = 0.f;

    for (int nn = 0; nn < 32; nn++) {
        int n = n0 + nn;
        __syncthreads();
        {
            float4 wv = *(const float4*)&W[(size_t)n * 1024 + tid * 4];
            int eo = tid >> 1, i0 = (tid & 1) * 4;
            sW[(i0 + 0) * 128 + eo] = wv.x;
            sW[(i0 + 1) * 128 + eo] = wv.y;
            sW[(i0 + 2) * 128 + eo] = wv.z;
            sW[(i0 + 3) * 128 + eo] = wv.w;
        }
        __syncthreads();

        float ureg = g_u[n * 256 + b0 * 8 + lane];

        float uh[4][4];
#pragma unroll
        for (int bb = 0; bb < 4; bb++)
#pragma unroll
            for (int ep = 0; ep < 4; ep++) uh[bb][ep] = 0.f;

#pragma unroll
        for (int i = 0; i < 8; i++) {
            float ub[4];
#pragma unroll
            for (int bb = 0; bb < 4; bb++)
                ub[bb] = __shfl_sync(0xffffffffu, ureg, bb * 8 + i);
#pragma unroll
            for (int ep = 0; ep < 4; ep++) {
                float w = sW[i * 128 + ep * 32 + lane];
#pragma unroll
                for (int bb = 0; bb < 4; bb++) uh[bb][ep] += ub[bb] * w;
            }
        }

        if (PASS == 0) {
#pragma unroll
            for (int bb = 0; bb < 4; bb++)
#pragma unroll
                for (int ep = 0; ep < 4; ep++) accS[bb][ep] += uh[bb][ep];
        } else {
#pragma unroll
            for (int bb = 0; bb < 4; bb++) {
                float a[4], m4 = -1e30f;
#pragma unroll
                for (int ep = 0; ep < 4; ep++) {
                    float p = uh[bb][ep] * vv0[bb][ep];
                    if (PASS == 2) p += uh[bb][ep] * vv1[bb][ep];
#pragma unroll
                    for (int off = 8; off; off >>= 1)
                        p += __shfl_xor_sync(0xffffffffu, p, off);
                    a[ep] = p;
                    m4 = fmaxf(m4, p);
                }
                float amax = fmaxf(m4, __shfl_xor_sync(0xffffffffu, m4, 16));
                float ex[4], s4 = 0.f;
#pragma unroll
                for (int ep = 0; ep < 4; ep++) { ex[ep] = __expf(a[ep] - amax); s4 += ex[ep]; }
                float Z = s4 + __shfl_xor_sync(0xffffffffu, s4, 16);
                float rZ = 1.f / Z;
#pragma unroll
                for (int ep = 0; ep < 4; ep++)
                    accS[bb][ep] += ex[ep] * rZ * uh[bb][ep];
            }
        }
    }

    float* Sout = (PASS == 0) ? g_S0 : (PASS == 1) ? g_S1 : g_S2;
#pragma unroll
    for (int bb = 0; bb < 4; bb++)
#pragma unroll
        for (int ep = 0; ep < 4; ep++)
            atomicAdd(&Sout[(b0 + bb) * 128 + ep * 32 + lane], accS[bb][ep]);
}

__global__ void k_squash(int which, float scale) {
    int b = blockIdx.x, t = threadIdx.x;
    const float* S = (which == 0) ? g_S0 : (which == 1) ? g_S1 : g_S2;
    float* V = (which == 0) ? g_v0 : (which == 1) ? g_v1 : g_v2;
    float s = S[b * 128 + t] * scale;
    float n2 = s * s;
#pragma unroll
    for (int off = 8; off; off >>= 1)
        n2 += __shfl_xor_sync(0xffffffffu, n2, off);
    float nn = sqrtf(n2);
    V[b * 128 + t] = (n2 / (1.f + n2)) * s / (nn + 1e-8f);
}

__global__ void k_final(float* __restrict__ out) {
    int b = blockIdx.x, t = threadIdx.x;
    float v = g_v2[b * 128 + t];
    float s = v * v;
#pragma unroll
    for (int off = 8; off; off >>= 1)
        s += __shfl_xor_sync(0xffffffffu, s, off);
    if ((t & 15) == 0) out[b * 8 + (t >> 4)] = sqrtf(s);
}

// ===========================================================================
extern "C" void kernel_launch(void* const* d_in, const int* in_sizes, int n_in,
                              void* d_out, int out_size) {
    const float* x   = (const float*)d_in[0];
    const float* w1  = (const float*)d_in[1];
    const float* b1  = (const float*)d_in[2];
    const float* w2  = (const float*)d_in[3];
    const float* b2  = (const float*)d_in[4];
    const float* w3  = (const float*)d_in[5];
    const float* b3  = (const float*)d_in[6];
    const float* pcw = (const float*)d_in[7];
    const float* pcb = (const float*)d_in[8];
    const float* W   = (const float*)d_in[9];
    float* out = (float*)d_out;

    cudaFuncSetAttribute(k_gemm2<0>, cudaFuncAttributeMaxDynamicSharedMemorySize, SMEM_GEMM);
    cudaFuncSetAttribute(k_gemm2<1>, cudaFuncAttributeMaxDynamicSharedMemorySize, SMEM_GEMM);

    k_zero_all<<<14400, 256>>>();
    k_conv1<<<dim3(32, 5), 256>>>(x, w1, b1);
    k_prep_w2s<<<256, 256>>>(w2);
    k_gemm2<0><<<dim3(148, 2), 256, SMEM_GEMM>>>(b2);   // conv2 (profiled slot)
    k_prep_w3s<<<512, 256>>>(w3);
    k_gemm2<1><<<dim3(148, 2), 256, SMEM_GEMM>>>(b3);   // conv3
    k_caps_u<<<2500, 256>>>(pcw, pcb);
    k_pass<0><<<625, 256>>>(W);
    k_squash<<<32, 128>>>(0, 0.125f);
    k_pass<1><<<625, 256>>>(W);
    k_squash<<<32, 128>>>(1, 1.f);
    k_pass<2><<<625, 256>>>(W);
    k_squash<<<32, 128>>>(2, 1.f);
    k_final<<<32, 128>>>(out);
}